// round 9
// baseline (speedup 1.0000x reference)
#include <cuda_runtime.h>
#include <cstdint>

// Problem dims
#define B_ 8
#define L_ 1024
#define D_ 512
#define H_ 8
#define DK_ 64
#define BL_ (B_ * L_)               // 8192
#define ATT_OFF ((size_t)BL_ * D_)  // start of attn in d_out

// GEMM tile config
#define BM 128
#define BN 64
#define BK 32
#define NTHR 256

#define ASZ (BM * 36)       // A stage floats
#define BSZ (BK * 72)       // B stage floats
#define SMEM_GEMM ((2 * ASZ + 2 * BSZ + 128) * 4)        // 55808 B
#define SMEM_SC   ((128 * 68 + 64 * 68 + 256) * 4)       // pass-1

// k_attn3 smem: Qp[4096] Pp[5120] Ks[64*68] Vs[64*72] rinv[64]
#define A3_QP 0
#define A3_PP 4096
#define A3_KS (A3_PP + 5120)
#define A3_VS (A3_KS + 64 * 68)
#define A3_RI (A3_VS + 64 * 72)
#define A3_SMEM ((A3_RI + 64) * 4)      // 72,960 B -> 3 CTAs/SM

// Scratch (static device globals — no allocation)
__device__ float g_Q[BL_ * D_];
__device__ float g_K[BL_ * D_];
__device__ float g_V[BL_ * D_];
__device__ float g_O[BL_ * D_];
__device__ float g_O2[BL_ * D_];
__device__ float g_X[BL_ * D_];
__device__ float g_lat[B_ * 2 * D_];
__device__ float g_psum[(size_t)B_ * H_ * 16 * L_];
__device__ float g_rinv[(size_t)B_ * H_ * L_];

// ---------------------------------------------------------------------------
// helpers
// ---------------------------------------------------------------------------
__device__ __forceinline__ float tf32r(float x) {
    uint32_t o;
    asm("cvt.rna.tf32.f32 %0, %1;" : "=r"(o) : "f"(x));
    return __uint_as_float(o);
}

__device__ __forceinline__ void mma_tf32(float c[4], const float a[4], const float b[2]) {
    asm volatile(
        "mma.sync.aligned.m16n8k8.row.col.f32.tf32.tf32.f32 "
        "{%0,%1,%2,%3}, {%4,%5,%6,%7}, {%8,%9}, {%0,%1,%2,%3};"
        : "+f"(c[0]), "+f"(c[1]), "+f"(c[2]), "+f"(c[3])
        : "r"(__float_as_uint(a[0])), "r"(__float_as_uint(a[1])),
          "r"(__float_as_uint(a[2])), "r"(__float_as_uint(a[3])),
          "r"(__float_as_uint(b[0])), "r"(__float_as_uint(b[1])));
}

__device__ __forceinline__ void cp16(float* dst_smem, const float* src) {
    uint32_t d = (uint32_t)__cvta_generic_to_shared(dst_smem);
    asm volatile("cp.async.cg.shared.global [%0], [%1], 16;" :: "r"(d), "l"(src));
}
#define CP_COMMIT() asm volatile("cp.async.commit_group;")
#define CP_WAIT0()  asm volatile("cp.async.wait_group 0;")
#define CP_WAIT1()  asm volatile("cp.async.wait_group 1;")

// ---------------------------------------------------------------------------
// Double-buffered cp.async TF32 GEMM. RND: round C to tf32 on store.
// ---------------------------------------------------------------------------
template <bool RND>
__device__ __forceinline__ void gemm_pipe(
    const float* __restrict__ A, const float* __restrict__ Bg,
    const float* __restrict__ bias, float* __restrict__ C,
    int K, int lda, int ldb, int ldc)
{
    extern __shared__ float sm[];
    float* Asm = sm;                    // [2][BM][36]
    float* Bsm = sm + 2 * ASZ;          // [2][BK][72]

    const int t = threadIdx.x;
    const int lane = t & 31, w = t >> 5;
    const int wm = w & 3, wn = w >> 2;
    const int g = lane >> 2, tg = lane & 3;
    const int row0 = blockIdx.y * BM;
    const int col0 = blockIdx.x * BN;

    float acc[2][4][4] = {};

    {
        #pragma unroll
        for (int i = 0; i < 4; i++) {
            int idx = t + i * NTHR, r = idx >> 3, c4 = (idx & 7) << 2;
            cp16(Asm + r * 36 + c4, A + (size_t)(row0 + r) * lda + c4);
        }
        #pragma unroll
        for (int i = 0; i < 2; i++) {
            int idx = t + i * NTHR, r = idx >> 4, c4 = (idx & 15) << 2;
            cp16(Bsm + r * 72 + c4, Bg + (size_t)r * ldb + col0 + c4);
        }
        CP_COMMIT();
    }

    int buf = 0;
    for (int k0 = 0; k0 < K; k0 += BK) {
        if (k0 + BK < K) {
            float* Ad = Asm + (buf ^ 1) * ASZ;
            float* Bd = Bsm + (buf ^ 1) * BSZ;
            int kn = k0 + BK;
            #pragma unroll
            for (int i = 0; i < 4; i++) {
                int idx = t + i * NTHR, r = idx >> 3, c4 = (idx & 7) << 2;
                cp16(Ad + r * 36 + c4, A + (size_t)(row0 + r) * lda + kn + c4);
            }
            #pragma unroll
            for (int i = 0; i < 2; i++) {
                int idx = t + i * NTHR, r = idx >> 4, c4 = (idx & 15) << 2;
                cp16(Bd + r * 72 + c4, Bg + (size_t)(kn + r) * ldb + col0 + c4);
            }
            CP_COMMIT();
            CP_WAIT1();
        } else {
            CP_WAIT0();
        }
        __syncthreads();

        float* Ab = Asm + buf * ASZ;
        float* Bb = Bsm + buf * BSZ;

        #pragma unroll
        for (int ks = 0; ks < BK; ks += 8) {
            float a[2][4], bf[4][2];
            #pragma unroll
            for (int mt = 0; mt < 2; mt++) {
                int r = wm * 32 + mt * 16 + g;
                a[mt][0] = tf32r(Ab[r * 36 + ks + tg]);
                a[mt][1] = tf32r(Ab[(r + 8) * 36 + ks + tg]);
                a[mt][2] = tf32r(Ab[r * 36 + ks + tg + 4]);
                a[mt][3] = tf32r(Ab[(r + 8) * 36 + ks + tg + 4]);
            }
            #pragma unroll
            for (int nt = 0; nt < 4; nt++) {
                int n = wn * 32 + nt * 8 + g;
                bf[nt][0] = tf32r(Bb[(ks + tg) * 72 + n]);
                bf[nt][1] = tf32r(Bb[(ks + tg + 4) * 72 + n]);
            }
            #pragma unroll
            for (int mt = 0; mt < 2; mt++)
                #pragma unroll
                for (int nt = 0; nt < 4; nt++)
                    mma_tf32(acc[mt][nt], a[mt], bf[nt]);
        }
        __syncthreads();
        buf ^= 1;
    }

    #pragma unroll
    for (int mt = 0; mt < 2; mt++) {
        #pragma unroll
        for (int nt = 0; nt < 4; nt++) {
            int r = row0 + wm * 32 + mt * 16 + g;
            int c = col0 + wn * 32 + nt * 8 + tg * 2;
            float b0 = 0.f, b1 = 0.f;
            if (bias) { b0 = bias[c]; b1 = bias[c + 1]; }
            float o0 = acc[mt][nt][0] + b0, o1 = acc[mt][nt][1] + b1;
            float o2 = acc[mt][nt][2] + b0, o3 = acc[mt][nt][3] + b1;
            if (RND) { o0 = tf32r(o0); o1 = tf32r(o1); o2 = tf32r(o2); o3 = tf32r(o3); }
            *(float2*)(C + (size_t)r * ldc + c) = make_float2(o0, o1);
            *(float2*)(C + (size_t)(r + 8) * ldc + c) = make_float2(o2, o3);
        }
    }
}

// ---------------------------------------------------------------------------
// Pass 1: row sums of exp(QK^T/8). grid (16, 8, 64). Q/K pre-rounded.
// ---------------------------------------------------------------------------
__global__ void __launch_bounds__(256) k_rsum() {
    extern __shared__ float sm[];
    float* Qs = sm;                     // [128][68]
    float* Ks = sm + 128 * 68;          // [64][68]
    float* sPart = Ks + 64 * 68;        // [2][128]

    const int t = threadIdx.x;
    const int lane = t & 31, w = t >> 5;
    const int wm = w & 3, wn = w >> 2;
    const int g = lane >> 2, tg = lane & 3;
    const int z = blockIdx.z, b = z >> 3, h = z & 7;
    const int row0 = blockIdx.y * 128;
    const int col0 = blockIdx.x * 64;

    const float* Qg = g_Q + (size_t)b * L_ * D_ + h * DK_;
    const float* Kg = g_K + (size_t)b * L_ * D_ + h * DK_;

    #pragma unroll
    for (int i = 0; i < 8; i++) {
        int idx = t + i * 256, r = idx >> 4, c4 = (idx & 15) << 2;
        cp16(Qs + r * 68 + c4, Qg + (size_t)(row0 + r) * D_ + c4);
    }
    #pragma unroll
    for (int i = 0; i < 4; i++) {
        int idx = t + i * 256, r = idx >> 4, c4 = (idx & 15) << 2;
        cp16(Ks + r * 68 + c4, Kg + (size_t)(col0 + r) * D_ + c4);
    }
    CP_COMMIT();
    CP_WAIT0();
    __syncthreads();

    float acc[2][4][4] = {};
    #pragma unroll
    for (int ks = 0; ks < DK_; ks += 8) {
        float a[2][4], bf[4][2];
        #pragma unroll
        for (int mt = 0; mt < 2; mt++) {
            int r = wm * 32 + mt * 16 + g;
            a[mt][0] = Qs[r * 68 + ks + tg];
            a[mt][1] = Qs[(r + 8) * 68 + ks + tg];
            a[mt][2] = Qs[r * 68 + ks + tg + 4];
            a[mt][3] = Qs[(r + 8) * 68 + ks + tg + 4];
        }
        #pragma unroll
        for (int nt = 0; nt < 4; nt++) {
            int n = wn * 32 + nt * 8 + g;
            bf[nt][0] = Ks[n * 68 + ks + tg];
            bf[nt][1] = Ks[n * 68 + ks + tg + 4];
        }
        #pragma unroll
        for (int mt = 0; mt < 2; mt++)
            #pragma unroll
            for (int nt = 0; nt < 4; nt++)
                mma_tf32(acc[mt][nt], a[mt], bf[nt]);
    }

    float rs[2][2] = {};
    #pragma unroll
    for (int mt = 0; mt < 2; mt++)
        #pragma unroll
        for (int nt = 0; nt < 4; nt++) {
            rs[mt][0] += __expf(acc[mt][nt][0] * 0.125f) + __expf(acc[mt][nt][1] * 0.125f);
            rs[mt][1] += __expf(acc[mt][nt][2] * 0.125f) + __expf(acc[mt][nt][3] * 0.125f);
        }
    #pragma unroll
    for (int mt = 0; mt < 2; mt++) {
        #pragma unroll
        for (int j = 0; j < 2; j++) {
            rs[mt][j] += __shfl_xor_sync(~0u, rs[mt][j], 1);
            rs[mt][j] += __shfl_xor_sync(~0u, rs[mt][j], 2);
        }
        if (tg == 0) {
            int rl = wm * 32 + mt * 16 + g;
            sPart[wn * 128 + rl] = rs[mt][0];
            sPart[wn * 128 + rl + 8] = rs[mt][1];
        }
    }
    __syncthreads();
    if (t < 128)
        g_psum[((size_t)z * 16 + blockIdx.x) * L_ + row0 + t] =
            sPart[t] + sPart[128 + t];
}

__global__ void k_rowsum() {
    int rid = blockIdx.x * 256 + threadIdx.x;
    int z = rid >> 10, r = rid & 1023;
    float s = 0.f;
    #pragma unroll
    for (int ct = 0; ct < 16; ct++)
        s += g_psum[((size_t)z * 16 + ct) * L_ + r];
    g_rinv[rid] = 1.0f / s;
}

// ---------------------------------------------------------------------------
// Pass 2 (v3): permuted fragment layouts + pipelined K/V.
// QB=64, chunk=64. grid (16, 64), 256 threads, 3 CTAs/SM.
// Qp/Pp hold a-operand fragments as float4: frag(rowgrp,ks,g,tg) =
//   { A[rg*16+g][ks*8+tg], A[rg*16+g+8][ks*8+tg],
//     A[rg*16+g][ks*8+tg+4], A[rg*16+g+8][ks*8+tg+4] }
// Qp: plain blocks of 128 floats; Pp: g-stride 20 (block 160) to tame STS.
// ---------------------------------------------------------------------------
__global__ void __launch_bounds__(256, 3) k_attn3(float* __restrict__ attn) {
    extern __shared__ float sm[];
    float* Qp = sm + A3_QP;
    float* Pp = sm + A3_PP;
    float* Ks = sm + A3_KS;      // [64][68], also Q staging at start
    float* Vs = sm + A3_VS;      // [64][72]
    float* sRinv = sm + A3_RI;   // [64]

    const int t = threadIdx.x;
    const int lane = t & 31, w = t >> 5;
    const int wm = w & 1, wn = w >> 1;           // 2(m) x 4(n)
    const int g = lane >> 2, tg = lane & 3;
    const int z = blockIdx.y, b = z >> 3, h = z & 7;
    const int row0 = blockIdx.x * 64;

    const float* Qg = g_Q + (size_t)b * L_ * D_ + h * DK_;
    const float* Kg = g_K + (size_t)b * L_ * D_ + h * DK_;
    const float* Vg = g_V + (size_t)b * L_ * D_ + h * DK_;
    float* attn_b = attn + (size_t)z * L_ * L_;

    if (t < 64) sRinv[t] = g_rinv[(size_t)z * L_ + row0 + t];

    // ---- stage Q linear into Ks, then build permuted Qp ----
    #pragma unroll
    for (int i = 0; i < 4; i++) {
        int idx = t + i * 256, r = idx >> 4, c4 = (idx & 15) << 2;
        cp16(Ks + r * 68 + c4, Qg + (size_t)(row0 + r) * D_ + c4);
    }
    CP_COMMIT();
    CP_WAIT0();
    __syncthreads();
    #pragma unroll
    for (int i = 0; i < 4; i++) {
        int fid = t + i * 256;
        int ftg = fid & 3, fg = (fid >> 2) & 7, fks = (fid >> 5) & 7, frg = fid >> 8;
        int r = frg * 16 + fg, c = fks * 8 + ftg;
        float4 v;
        v.x = Ks[r * 68 + c];
        v.y = Ks[(r + 8) * 68 + c];
        v.z = Ks[r * 68 + c + 4];
        v.w = Ks[(r + 8) * 68 + c + 4];
        ((float4*)Qp)[fid] = v;
    }
    __syncthreads();

    // ---- kick K0, V0 (separate groups) ----
    #pragma unroll
    for (int i = 0; i < 4; i++) {
        int idx = t + i * 256, r = idx >> 4, c4 = (idx & 15) << 2;
        cp16(Ks + r * 68 + c4, Kg + (size_t)r * D_ + c4);
    }
    CP_COMMIT();
    #pragma unroll
    for (int i = 0; i < 4; i++) {
        int idx = t + i * 256, r = idx >> 4, c4 = (idx & 15) << 2;
        cp16(Vs + r * 72 + c4, Vg + (size_t)r * D_ + c4);
    }
    CP_COMMIT();

    // per-thread P writer constants
    const int sc2 = (tg < 2) ? 0 : 2;                 // slotcol*2
    const int tgp0 = (tg < 2) ? 2 * tg : 2 * tg - 4;
    const int tgp1 = tgp0 + 1;

    float accO[2][2][4] = {};

    for (int kc = 0; kc < 16; kc++) {
        CP_WAIT1();          // K_kc done (V_kc may be pending)
        __syncthreads();

        // ---- S tile (64x64) = Q Kt ----
        float acc[2][2][4] = {};
        #pragma unroll
        for (int ks = 0; ks < 8; ks++) {
            float4 afr[2];
            #pragma unroll
            for (int mt = 0; mt < 2; mt++)
                afr[mt] = *(const float4*)(Qp + ((wm * 2 + mt) * 8 + ks) * 128 + g * 16 + tg * 4);
            float bf[2][2];
            #pragma unroll
            for (int nt = 0; nt < 2; nt++) {
                int n = wn * 16 + nt * 8 + g;
                bf[nt][0] = Ks[n * 68 + ks * 8 + tg];
                bf[nt][1] = Ks[n * 68 + ks * 8 + tg + 4];
            }
            #pragma unroll
            for (int mt = 0; mt < 2; mt++)
                #pragma unroll
                for (int nt = 0; nt < 2; nt++)
                    mma_tf32(acc[mt][nt], (const float*)&afr[mt], bf[nt]);
        }

        // ---- P = exp(S/8)*rinv: write gmem attn (exact) + Pp (tf32) ----
        #pragma unroll
        for (int mt = 0; mt < 2; mt++) {
            int rl = wm * 32 + mt * 16 + g;
            float r0 = sRinv[rl], r1 = sRinv[rl + 8];
            #pragma unroll
            for (int nt = 0; nt < 2; nt++) {
                float e0 = __expf(acc[mt][nt][0] * 0.125f) * r0;
                float e1 = __expf(acc[mt][nt][1] * 0.125f) * r0;
                float e2 = __expf(acc[mt][nt][2] * 0.125f) * r1;
                float e3 = __expf(acc[mt][nt][3] * 0.125f) * r1;
                int col = kc * 64 + wn * 16 + nt * 8 + 2 * tg;
                *(float2*)(attn_b + (size_t)(row0 + rl) * L_ + col) = make_float2(e0, e1);
                *(float2*)(attn_b + (size_t)(row0 + rl + 8) * L_ + col) = make_float2(e2, e3);
                int blkg = ((wm * 2 + mt) * 8 + (wn * 2 + nt)) * 160 + g * 20;
                Pp[blkg + tgp0 * 4 + sc2]     = tf32r(e0);
                Pp[blkg + tgp1 * 4 + sc2]     = tf32r(e1);
                Pp[blkg + tgp0 * 4 + sc2 + 1] = tf32r(e2);
                Pp[blkg + tgp1 * 4 + sc2 + 1] = tf32r(e3);
            }
        }
        __syncthreads();     // Pp ready; Ks free

        // ---- prefetch next K (overlaps with O-MMA), wait for V_kc ----
        if (kc < 15) {
            #pragma unroll
            for (int i = 0; i < 4; i++) {
                int idx = t + i * 256, r = idx >> 4, c4 = (idx & 15) << 2;
                cp16(Ks + r * 68 + c4, Kg + (size_t)((kc + 1) * 64 + r) * D_ + c4);
            }
            CP_COMMIT();
            CP_WAIT1();      // V_kc done (K_{kc+1} pending)
        } else {
            CP_WAIT0();      // V_15 done
        }
        __syncthreads();

        // ---- O += P @ V ----
        #pragma unroll
        for (int ks = 0; ks < 8; ks++) {
            float4 afr[2];
            #pragma unroll
            for (int mt = 0; mt < 2; mt++)
                afr[mt] = *(const float4*)(Pp + ((wm * 2 + mt) * 8 + ks) * 160 + g * 20 + tg * 4);
            float bf[2][2];
            #pragma unroll
            for (int nt = 0; nt < 2; nt++) {
                int n = wn * 16 + nt * 8 + g;
                bf[nt][0] = Vs[(ks * 8 + tg) * 72 + n];
                bf[nt][1] = Vs[(ks * 8 + tg + 4) * 72 + n];
            }
            #pragma unroll
            for (int mt = 0; mt < 2; mt++)
                #pragma unroll
                for (int nt = 0; nt < 2; nt++)
                    mma_tf32(accO[mt][nt], (const float*)&afr[mt], bf[nt]);
        }
        __syncthreads();     // Vs free

        if (kc < 15) {
            #pragma unroll
            for (int i = 0; i < 4; i++) {
                int idx = t + i * 256, r = idx >> 4, c4 = (idx & 15) << 2;
                cp16(Vs + r * 72 + c4, Vg + (size_t)((kc + 1) * 64 + r) * D_ + c4);
            }
            CP_COMMIT();
        }
    }

    // ---- epilogue: write O ----
    #pragma unroll
    for (int mt = 0; mt < 2; mt++) {
        #pragma unroll
        for (int nt = 0; nt < 2; nt++) {
            int rl = wm * 32 + mt * 16 + g;
            int c = wn * 16 + nt * 8 + tg * 2;
            float* Og = g_O + (size_t)(b * L_ + row0 + rl) * D_ + h * DK_ + c;
            *(float2*)Og = make_float2(accO[mt][nt][0], accO[mt][nt][1]);
            *(float2*)(Og + 8 * D_) = make_float2(accO[mt][nt][2], accO[mt][nt][3]);
        }
    }
}

// ---------------------------------------------------------------------------
// GEMM wrappers
// ---------------------------------------------------------------------------
__global__ void __launch_bounds__(NTHR) k_proj_qkv(
        const float* __restrict__ q, const float* __restrict__ k,
        const float* __restrict__ v,
        const float* __restrict__ Wq, const float* __restrict__ Wk,
        const float* __restrict__ Wv,
        const float* __restrict__ bq, const float* __restrict__ bk,
        const float* __restrict__ bv) {
    int z = blockIdx.z;
    const float* A = (z == 0) ? q : (z == 1) ? k : v;
    const float* W = (z == 0) ? Wq : (z == 1) ? Wk : Wv;
    const float* bias = (z == 0) ? bq : (z == 1) ? bk : bv;
    float* C = (z == 0) ? g_Q : (z == 1) ? g_K : g_V;
    gemm_pipe<true>(A, W, bias, C, D_, D_, D_, D_);
}

__global__ void __launch_bounds__(NTHR) k_fc(const float* __restrict__ W,
        const float* __restrict__ bias) {
    gemm_pipe<false>(g_O, W, bias, g_O2, D_, D_, D_, D_);
}
__global__ void __launch_bounds__(NTHR) k_s2(const float* __restrict__ W,
        const float* __restrict__ bias) {
    gemm_pipe<false>(g_X, W, bias, g_O, D_, D_, D_, D_);
}

// ---------------------------------------------------------------------------
// small epilogues
// ---------------------------------------------------------------------------
__global__ void k_lat(const float* __restrict__ latent, const float* __restrict__ Ws1,
                      const float* __restrict__ bs1) {
    int b = blockIdx.x;
    __shared__ float sl[D_];
    for (int i = threadIdx.x; i < D_; i += 128) {
        float x = latent[b * D_ + i];
        sl[i] = x / (1.0f + __expf(-x));
    }
    __syncthreads();
    int j = blockIdx.y * 128 + threadIdx.x;
    float acc = bs1[j];
    for (int k = 0; k < D_; k++) acc += sl[k] * Ws1[(size_t)k * (2 * D_) + j];
    g_lat[b * (2 * D_) + j] = acc;
}

__global__ void k_film(const float* __restrict__ en_g, const float* __restrict__ en_b) {
    int row = blockIdx.x;
    int b = row >> 10;
    int t = threadIdx.x;
    float4 v = ((const float4*)(g_O2 + (size_t)row * D_))[t];
    __shared__ float red[128];

    red[t] = v.x + v.y + v.z + v.w;
    __syncthreads();
    for (int s = 64; s > 0; s >>= 1) {
        if (t < s) red[t] += red[t + s];
        __syncthreads();
    }
    float mean = red[0] * (1.0f / D_);
    __syncthreads();

    float dx = v.x - mean, dy = v.y - mean, dz = v.z - mean, dw = v.w - mean;
    red[t] = dx * dx + dy * dy + dz * dz + dw * dw;
    __syncthreads();
    for (int s = 64; s > 0; s >>= 1) {
        if (t < s) red[t] += red[t + s];
        __syncthreads();
    }
    float rstd = rsqrtf(red[0] * (1.0f / D_) + 1e-5f);

    int j = t * 4;
    float4 g4 = ((const float4*)en_g)[t];
    float4 b4 = ((const float4*)en_b)[t];
    float4 sc = *(const float4*)(g_lat + b * (2 * D_) + j);
    float4 sh = *(const float4*)(g_lat + b * (2 * D_) + D_ + j);

    float4 o;
    {
        float h;
        h = (dx * rstd * g4.x + b4.x) * (1.0f + sc.x) + sh.x; o.x = h / (1.0f + __expf(-h));
        h = (dy * rstd * g4.y + b4.y) * (1.0f + sc.y) + sh.y; o.y = h / (1.0f + __expf(-h));
        h = (dz * rstd * g4.z + b4.z) * (1.0f + sc.z) + sh.z; o.z = h / (1.0f + __expf(-h));
        h = (dw * rstd * g4.w + b4.w) * (1.0f + sc.w) + sh.w; o.w = h / (1.0f + __expf(-h));
    }
    ((float4*)(g_X + (size_t)row * D_))[t] = o;
}

__global__ void k_final(const float* __restrict__ resid, const float* __restrict__ ln_g,
                        const float* __restrict__ ln_b, float* __restrict__ out) {
    int row = blockIdx.x;
    int t = threadIdx.x;
    float4 v = ((const float4*)(g_O + (size_t)row * D_))[t];
    float4 r = ((const float4*)(resid + (size_t)row * D_))[t];
    v.x += r.x; v.y += r.y; v.z += r.z; v.w += r.w;
    __shared__ float red[128];

    red[t] = v.x + v.y + v.z + v.w;
    __syncthreads();
    for (int s = 64; s > 0; s >>= 1) {
        if (t < s) red[t] += red[t + s];
        __syncthreads();
    }
    float mean = red[0] * (1.0f / D_);
    __syncthreads();

    float dx = v.x - mean, dy = v.y - mean, dz = v.z - mean, dw = v.w - mean;
    red[t] = dx * dx + dy * dy + dz * dz + dw * dw;
    __syncthreads();
    for (int s = 64; s > 0; s >>= 1) {
        if (t < s) red[t] += red[t + s];
        __syncthreads();
    }
    float rstd = rsqrtf(red[0] * (1.0f / D_) + 1e-6f);

    float4 g4 = ((const float4*)ln_g)[t];
    float4 b4 = ((const float4*)ln_b)[t];
    float4 o;
    o.x = dx * rstd * g4.x + b4.x;
    o.y = dy * rstd * g4.y + b4.y;
    o.z = dz * rstd * g4.z + b4.z;
    o.w = dw * rstd * g4.w + b4.w;
    ((float4*)(out + (size_t)row * D_))[t] = o;
}

// ---------------------------------------------------------------------------
extern "C" void kernel_launch(void* const* d_in, const int* in_sizes, int n_in,
                              void* d_out, int out_size) {
    const float* q      = (const float*)d_in[0];
    const float* k      = (const float*)d_in[1];
    const float* v      = (const float*)d_in[2];
    const float* latent = (const float*)d_in[3];
    const float* Wq  = (const float*)d_in[4];
    const float* bq  = (const float*)d_in[5];
    const float* Wk  = (const float*)d_in[6];
    const float* bk  = (const float*)d_in[7];
    const float* Wv  = (const float*)d_in[8];
    const float* bv  = (const float*)d_in[9];
    const float* Wfc = (const float*)d_in[10];
    const float* bfc = (const float*)d_in[11];
    const float* Ws1 = (const float*)d_in[12];
    const float* bs1 = (const float*)d_in[13];
    const float* Ws2 = (const float*)d_in[14];
    const float* bs2 = (const float*)d_in[15];
    const float* en_g = (const float*)d_in[16];
    const float* en_b = (const float*)d_in[17];
    const float* ln_g = (const float*)d_in[18];
    const float* ln_b = (const float*)d_in[19];

    float* out  = (float*)d_out;
    float* attn = out + ATT_OFF;

    cudaFuncSetAttribute(k_proj_qkv, cudaFuncAttributeMaxDynamicSharedMemorySize, SMEM_GEMM);
    cudaFuncSetAttribute(k_fc,   cudaFuncAttributeMaxDynamicSharedMemorySize, SMEM_GEMM);
    cudaFuncSetAttribute(k_s2,   cudaFuncAttributeMaxDynamicSharedMemorySize, SMEM_GEMM);
    cudaFuncSetAttribute(k_rsum, cudaFuncAttributeMaxDynamicSharedMemorySize, SMEM_SC);
    cudaFuncSetAttribute(k_attn3, cudaFuncAttributeMaxDynamicSharedMemorySize, A3_SMEM);

    dim3 t256(NTHR);
    dim3 gProj(D_ / BN, BL_ / BM);          // (8, 64)

    k_proj_qkv<<<dim3(D_ / BN, BL_ / BM, 3), t256, SMEM_GEMM>>>(
        q, k, v, Wq, Wk, Wv, bq, bk, bv);

    k_rsum<<<dim3(L_ / 64, L_ / 128, B_ * H_), t256, SMEM_SC>>>();
    k_rowsum<<<(B_ * H_ * L_) / 256, 256>>>();
    k_attn3<<<dim3(L_ / 64, B_ * H_), t256, A3_SMEM>>>(attn);

    k_fc<<<gProj, t256, SMEM_GEMM>>>(Wfc, bfc);
    k_lat<<<dim3(B_, 8), 128>>>(latent, Ws1, bs1);
    k_film<<<BL_, 128>>>(en_g, en_b);
    k_s2<<<gProj, t256, SMEM_GEMM>>>(Ws2, bs2);
    k_final<<<BL_, 128>>>(q, ln_g, ln_b, out);
}

// round 10
// speedup vs baseline: 1.1224x; 1.1224x over previous
#include <cuda_runtime.h>
#include <cstdint>

// Problem dims
#define B_ 8
#define L_ 1024
#define D_ 512
#define H_ 8
#define DK_ 64
#define BL_ (B_ * L_)               // 8192
#define ATT_OFF ((size_t)BL_ * D_)  // start of attn in d_out

#define NTHR 256

// attnv pipe GEMM tile (128x64)
#define BM 128
#define BN 64
#define BK 32
#define ASZ (BM * 36)
#define BSZ (BK * 72)
#define SMEM_GEMM ((2 * ASZ + 2 * BSZ + 128) * 4)        // 55808 B

// big GEMM tile (128x128)
#define ABZ (128 * 36)
#define BBZ (32 * 136)
#define SMEM_BIG ((2 * ABZ + 2 * BBZ + 32) * 4)          // 71808 B

#define SMEM_SC   ((128 * 68 + 64 * 68 + 256) * 4)       // scores

// Scratch (static device globals — no allocation)
__device__ float g_Q[BL_ * D_];
__device__ float g_K[BL_ * D_];
__device__ float g_V[BL_ * D_];
__device__ float g_O[BL_ * D_];
__device__ float g_O2[BL_ * D_];
__device__ float g_X[BL_ * D_];
__device__ float g_lat[B_ * 2 * D_];
__device__ float g_psum[(size_t)B_ * H_ * 16 * L_];
__device__ float g_rinv[(size_t)B_ * H_ * L_];

// ---------------------------------------------------------------------------
// helpers
// ---------------------------------------------------------------------------
__device__ __forceinline__ float tf32r(float x) {
    uint32_t o;
    asm("cvt.rna.tf32.f32 %0, %1;" : "=r"(o) : "f"(x));
    return __uint_as_float(o);
}

__device__ __forceinline__ void mma_tf32(float c[4], const float a[4], const float b[2]) {
    asm volatile(
        "mma.sync.aligned.m16n8k8.row.col.f32.tf32.tf32.f32 "
        "{%0,%1,%2,%3}, {%4,%5,%6,%7}, {%8,%9}, {%0,%1,%2,%3};"
        : "+f"(c[0]), "+f"(c[1]), "+f"(c[2]), "+f"(c[3])
        : "r"(__float_as_uint(a[0])), "r"(__float_as_uint(a[1])),
          "r"(__float_as_uint(a[2])), "r"(__float_as_uint(a[3])),
          "r"(__float_as_uint(b[0])), "r"(__float_as_uint(b[1])));
}

__device__ __forceinline__ void cp16(float* dst_smem, const float* src) {
    uint32_t d = (uint32_t)__cvta_generic_to_shared(dst_smem);
    asm volatile("cp.async.cg.shared.global [%0], [%1], 16;" :: "r"(d), "l"(src));
}
#define CP_COMMIT() asm volatile("cp.async.commit_group;")
#define CP_WAIT0()  asm volatile("cp.async.wait_group 0;")
#define CP_WAIT1()  asm volatile("cp.async.wait_group 1;")

// ---------------------------------------------------------------------------
// 128x64 double-buffered GEMM (attnv). SC: scale output rows by rinv and
// write back normalized A (attn) as it streams through.
// ---------------------------------------------------------------------------
template <bool SC>
__device__ __forceinline__ void gemm_pipe(
    const float* __restrict__ A, const float* __restrict__ Bg,
    const float* __restrict__ bias, float* __restrict__ C,
    int K, int lda, int ldb, int ldc,
    const float* __restrict__ rinvg, float* __restrict__ wback)
{
    extern __shared__ float sm[];
    float* Asm = sm;                    // [2][BM][36]
    float* Bsm = sm + 2 * ASZ;          // [2][BK][72]
    float* sRinv = Bsm + 2 * BSZ;       // [128]

    const int t = threadIdx.x;
    const int lane = t & 31, w = t >> 5;
    const int wm = w & 3, wn = w >> 2;
    const int g = lane >> 2, tg = lane & 3;
    const int row0 = blockIdx.y * BM;
    const int col0 = blockIdx.x * BN;

    if (SC && t < BM) sRinv[t] = rinvg[row0 + t];

    float acc[2][4][4] = {};

    {
        #pragma unroll
        for (int i = 0; i < 4; i++) {
            int idx = t + i * NTHR, r = idx >> 3, c4 = (idx & 7) << 2;
            cp16(Asm + r * 36 + c4, A + (size_t)(row0 + r) * lda + c4);
        }
        #pragma unroll
        for (int i = 0; i < 2; i++) {
            int idx = t + i * NTHR, r = idx >> 4, c4 = (idx & 15) << 2;
            cp16(Bsm + r * 72 + c4, Bg + (size_t)r * ldb + col0 + c4);
        }
        CP_COMMIT();
    }

    int buf = 0;
    for (int k0 = 0; k0 < K; k0 += BK) {
        if (k0 + BK < K) {
            float* Ad = Asm + (buf ^ 1) * ASZ;
            float* Bd = Bsm + (buf ^ 1) * BSZ;
            int kn = k0 + BK;
            #pragma unroll
            for (int i = 0; i < 4; i++) {
                int idx = t + i * NTHR, r = idx >> 3, c4 = (idx & 7) << 2;
                cp16(Ad + r * 36 + c4, A + (size_t)(row0 + r) * lda + kn + c4);
            }
            #pragma unroll
            for (int i = 0; i < 2; i++) {
                int idx = t + i * NTHR, r = idx >> 4, c4 = (idx & 15) << 2;
                cp16(Bd + r * 72 + c4, Bg + (size_t)(kn + r) * ldb + col0 + c4);
            }
            CP_COMMIT();
            CP_WAIT1();
        } else {
            CP_WAIT0();
        }
        __syncthreads();

        float* Ab = Asm + buf * ASZ;
        float* Bb = Bsm + buf * BSZ;

        if (SC) {
            // write normalized attn chunk back to gmem (coalesced float4)
            #pragma unroll
            for (int i = 0; i < 4; i++) {
                int idx = t + i * NTHR, r = idx >> 3, c4 = (idx & 7) << 2;
                float4 v = *(const float4*)(Ab + r * 36 + c4);
                float s = sRinv[r];
                v.x *= s; v.y *= s; v.z *= s; v.w *= s;
                *(float4*)(wback + (size_t)(row0 + r) * lda + k0 + c4) = v;
            }
        }

        #pragma unroll
        for (int ks = 0; ks < BK; ks += 8) {
            float a[2][4], bf[4][2];
            #pragma unroll
            for (int mt = 0; mt < 2; mt++) {
                int r = wm * 32 + mt * 16 + g;
                a[mt][0] = tf32r(Ab[r * 36 + ks + tg]);
                a[mt][1] = tf32r(Ab[(r + 8) * 36 + ks + tg]);
                a[mt][2] = tf32r(Ab[r * 36 + ks + tg + 4]);
                a[mt][3] = tf32r(Ab[(r + 8) * 36 + ks + tg + 4]);
            }
            #pragma unroll
            for (int nt = 0; nt < 4; nt++) {
                int n = wn * 32 + nt * 8 + g;
                bf[nt][0] = tf32r(Bb[(ks + tg) * 72 + n]);
                bf[nt][1] = tf32r(Bb[(ks + tg + 4) * 72 + n]);
            }
            #pragma unroll
            for (int mt = 0; mt < 2; mt++)
                #pragma unroll
                for (int nt = 0; nt < 4; nt++)
                    mma_tf32(acc[mt][nt], a[mt], bf[nt]);
        }
        __syncthreads();
        buf ^= 1;
    }

    #pragma unroll
    for (int mt = 0; mt < 2; mt++) {
        #pragma unroll
        for (int nt = 0; nt < 4; nt++) {
            int rl = wm * 32 + mt * 16 + g;
            int r = row0 + rl;
            int c = col0 + wn * 32 + nt * 8 + tg * 2;
            float s0 = 1.f, s1 = 1.f;
            if (SC) { s0 = sRinv[rl]; s1 = sRinv[rl + 8]; }
            float b0 = 0.f, b1 = 0.f;
            if (bias) { b0 = bias[c]; b1 = bias[c + 1]; }
            *(float2*)(C + (size_t)r * ldc + c) =
                make_float2(acc[mt][nt][0] * s0 + b0, acc[mt][nt][1] * s0 + b1);
            *(float2*)(C + (size_t)(r + 8) * ldc + c) =
                make_float2(acc[mt][nt][2] * s1 + b0, acc[mt][nt][3] * s1 + b1);
        }
    }
}

// ---------------------------------------------------------------------------
// 128x128 double-buffered GEMM (projections / fc / s2). Warp tile 32x64.
// RND: round C to tf32 on store (Q/K/V so downstream skips cvt).
// ---------------------------------------------------------------------------
template <bool RND>
__device__ __forceinline__ void gemm_big(
    const float* __restrict__ A, const float* __restrict__ Bg,
    const float* __restrict__ bias, float* __restrict__ C,
    int K, int lda, int ldb, int ldc)
{
    extern __shared__ float sm[];
    float* Asm = sm;                    // [2][128][36]
    float* Bsm = sm + 2 * ABZ;          // [2][32][136]

    const int t = threadIdx.x;
    const int lane = t & 31, w = t >> 5;
    const int wm = w & 3, wn = w >> 2;          // 4(m) x 2(n)
    const int g = lane >> 2, tg = lane & 3;
    const int row0 = blockIdx.y * 128;
    const int col0 = blockIdx.x * 128;

    float acc[2][8][4] = {};

    {
        #pragma unroll
        for (int i = 0; i < 4; i++) {
            int idx = t + i * NTHR, r = idx >> 3, c4 = (idx & 7) << 2;
            cp16(Asm + r * 36 + c4, A + (size_t)(row0 + r) * lda + c4);
        }
        #pragma unroll
        for (int i = 0; i < 4; i++) {
            int idx = t + i * NTHR, r = idx >> 5, c4 = (idx & 31) << 2;
            cp16(Bsm + r * 136 + c4, Bg + (size_t)r * ldb + col0 + c4);
        }
        CP_COMMIT();
    }

    int buf = 0;
    for (int k0 = 0; k0 < K; k0 += 32) {
        if (k0 + 32 < K) {
            float* Ad = Asm + (buf ^ 1) * ABZ;
            float* Bd = Bsm + (buf ^ 1) * BBZ;
            int kn = k0 + 32;
            #pragma unroll
            for (int i = 0; i < 4; i++) {
                int idx = t + i * NTHR, r = idx >> 3, c4 = (idx & 7) << 2;
                cp16(Ad + r * 36 + c4, A + (size_t)(row0 + r) * lda + kn + c4);
            }
            #pragma unroll
            for (int i = 0; i < 4; i++) {
                int idx = t + i * NTHR, r = idx >> 5, c4 = (idx & 31) << 2;
                cp16(Bd + r * 136 + c4, Bg + (size_t)(kn + r) * ldb + col0 + c4);
            }
            CP_COMMIT();
            CP_WAIT1();
        } else {
            CP_WAIT0();
        }
        __syncthreads();

        float* Ab = Asm + buf * ABZ;
        float* Bb = Bsm + buf * BBZ;

        #pragma unroll
        for (int ks = 0; ks < 32; ks += 8) {
            float a[2][4], bf[8][2];
            #pragma unroll
            for (int mt = 0; mt < 2; mt++) {
                int r = wm * 32 + mt * 16 + g;
                a[mt][0] = tf32r(Ab[r * 36 + ks + tg]);
                a[mt][1] = tf32r(Ab[(r + 8) * 36 + ks + tg]);
                a[mt][2] = tf32r(Ab[r * 36 + ks + tg + 4]);
                a[mt][3] = tf32r(Ab[(r + 8) * 36 + ks + tg + 4]);
            }
            #pragma unroll
            for (int nt = 0; nt < 8; nt++) {
                int n = wn * 64 + nt * 8 + g;
                bf[nt][0] = tf32r(Bb[(ks + tg) * 136 + n]);
                bf[nt][1] = tf32r(Bb[(ks + tg + 4) * 136 + n]);
            }
            #pragma unroll
            for (int mt = 0; mt < 2; mt++)
                #pragma unroll
                for (int nt = 0; nt < 8; nt++)
                    mma_tf32(acc[mt][nt], a[mt], bf[nt]);
        }
        __syncthreads();
        buf ^= 1;
    }

    #pragma unroll
    for (int mt = 0; mt < 2; mt++) {
        #pragma unroll
        for (int nt = 0; nt < 8; nt++) {
            int r = row0 + wm * 32 + mt * 16 + g;
            int c = col0 + wn * 64 + nt * 8 + tg * 2;
            float b0 = 0.f, b1 = 0.f;
            if (bias) { b0 = bias[c]; b1 = bias[c + 1]; }
            float o0 = acc[mt][nt][0] + b0, o1 = acc[mt][nt][1] + b1;
            float o2 = acc[mt][nt][2] + b0, o3 = acc[mt][nt][3] + b1;
            if (RND) { o0 = tf32r(o0); o1 = tf32r(o1); o2 = tf32r(o2); o3 = tf32r(o3); }
            *(float2*)(C + (size_t)r * ldc + c) = make_float2(o0, o1);
            *(float2*)(C + (size_t)(r + 8) * ldc + c) = make_float2(o2, o3);
        }
    }
}

// ---------------------------------------------------------------------------
// scores: E = exp(QK^T/8), staged coalesced write + partial row sums.
// grid (16 coltiles, 8 rowtiles, 64 heads). Q/K pre-rounded (no cvt).
// ---------------------------------------------------------------------------
__global__ void __launch_bounds__(256) k_scores(float* __restrict__ attn) {
    extern __shared__ float sm[];
    float* Qs = sm;                     // [128][68], reused to stage E
    float* Ks = sm + 128 * 68;          // [64][68]
    float* sPart = Ks + 64 * 68;        // [2][128]

    const int t = threadIdx.x;
    const int lane = t & 31, w = t >> 5;
    const int wm = w & 3, wn = w >> 2;
    const int g = lane >> 2, tg = lane & 3;
    const int z = blockIdx.z, b = z >> 3, h = z & 7;
    const int row0 = blockIdx.y * 128;
    const int col0 = blockIdx.x * 64;

    const float* Qg = g_Q + (size_t)b * L_ * D_ + h * DK_;
    const float* Kg = g_K + (size_t)b * L_ * D_ + h * DK_;
    float* attn_b = attn + (size_t)z * L_ * L_;

    #pragma unroll
    for (int i = 0; i < 8; i++) {
        int idx = t + i * 256, r = idx >> 4, c4 = (idx & 15) << 2;
        cp16(Qs + r * 68 + c4, Qg + (size_t)(row0 + r) * D_ + c4);
    }
    #pragma unroll
    for (int i = 0; i < 4; i++) {
        int idx = t + i * 256, r = idx >> 4, c4 = (idx & 15) << 2;
        cp16(Ks + r * 68 + c4, Kg + (size_t)(col0 + r) * D_ + c4);
    }
    CP_COMMIT();
    CP_WAIT0();
    __syncthreads();

    float acc[2][4][4] = {};
    #pragma unroll
    for (int ks = 0; ks < DK_; ks += 8) {
        float a[2][4], bf[4][2];
        #pragma unroll
        for (int mt = 0; mt < 2; mt++) {
            int r = wm * 32 + mt * 16 + g;
            a[mt][0] = Qs[r * 68 + ks + tg];
            a[mt][1] = Qs[(r + 8) * 68 + ks + tg];
            a[mt][2] = Qs[r * 68 + ks + tg + 4];
            a[mt][3] = Qs[(r + 8) * 68 + ks + tg + 4];
        }
        #pragma unroll
        for (int nt = 0; nt < 4; nt++) {
            int n = wn * 32 + nt * 8 + g;
            bf[nt][0] = Ks[n * 68 + ks + tg];
            bf[nt][1] = Ks[n * 68 + ks + tg + 4];
        }
        #pragma unroll
        for (int mt = 0; mt < 2; mt++)
            #pragma unroll
            for (int nt = 0; nt < 4; nt++)
                mma_tf32(acc[mt][nt], a[mt], bf[nt]);
    }
    __syncthreads();    // all warps done reading Qs; reuse it as staging

    // exp epilogue: stage E into Qs, accumulate partial row sums
    float rs[2][2] = {};
    #pragma unroll
    for (int mt = 0; mt < 2; mt++) {
        int rl = wm * 32 + mt * 16 + g;
        #pragma unroll
        for (int nt = 0; nt < 4; nt++) {
            int c = wn * 32 + nt * 8 + tg * 2;
            float e0 = __expf(acc[mt][nt][0] * 0.125f);
            float e1 = __expf(acc[mt][nt][1] * 0.125f);
            float e2 = __expf(acc[mt][nt][2] * 0.125f);
            float e3 = __expf(acc[mt][nt][3] * 0.125f);
            Qs[rl * 68 + c]           = e0;
            Qs[rl * 68 + c + 1]       = e1;
            Qs[(rl + 8) * 68 + c]     = e2;
            Qs[(rl + 8) * 68 + c + 1] = e3;
            rs[mt][0] += e0 + e1;
            rs[mt][1] += e2 + e3;
        }
    }
    #pragma unroll
    for (int mt = 0; mt < 2; mt++) {
        #pragma unroll
        for (int j = 0; j < 2; j++) {
            rs[mt][j] += __shfl_xor_sync(~0u, rs[mt][j], 1);
            rs[mt][j] += __shfl_xor_sync(~0u, rs[mt][j], 2);
        }
        if (tg == 0) {
            int rl = wm * 32 + mt * 16 + g;
            sPart[wn * 128 + rl] = rs[mt][0];
            sPart[wn * 128 + rl + 8] = rs[mt][1];
        }
    }
    __syncthreads();

    // coalesced write: 128 rows x 64 cols of E
    #pragma unroll
    for (int i = 0; i < 8; i++) {
        int idx = t + i * 256, r = idx >> 4, c4 = (idx & 15) << 2;
        *(float4*)(attn_b + (size_t)(row0 + r) * L_ + col0 + c4) =
            *(const float4*)(Qs + r * 68 + c4);
    }
    if (t < 128)
        g_psum[((size_t)z * 16 + blockIdx.x) * L_ + row0 + t] =
            sPart[t] + sPart[128 + t];
}

__global__ void k_rowsum() {
    int rid = blockIdx.x * 256 + threadIdx.x;
    int z = rid >> 10, r = rid & 1023;
    float s = 0.f;
    #pragma unroll
    for (int ct = 0; ct < 16; ct++)
        s += g_psum[((size_t)z * 16 + ct) * L_ + r];
    g_rinv[rid] = 1.0f / s;
}

// ---------------------------------------------------------------------------
// GEMM wrappers
// ---------------------------------------------------------------------------
__global__ void __launch_bounds__(NTHR, 2) k_proj_qkv(
        const float* __restrict__ q, const float* __restrict__ k,
        const float* __restrict__ v,
        const float* __restrict__ Wq, const float* __restrict__ Wk,
        const float* __restrict__ Wv,
        const float* __restrict__ bq, const float* __restrict__ bk,
        const float* __restrict__ bv) {
    int z = blockIdx.z;
    const float* A = (z == 0) ? q : (z == 1) ? k : v;
    const float* W = (z == 0) ? Wq : (z == 1) ? Wk : Wv;
    const float* bias = (z == 0) ? bq : (z == 1) ? bk : bv;
    float* C = (z == 0) ? g_Q : (z == 1) ? g_K : g_V;
    gemm_big<true>(A, W, bias, C, D_, D_, D_, D_);
}

// O = (E @ V) * rinv; also writes normalized attn. grid (1, 8, 64)
__global__ void __launch_bounds__(NTHR) k_attnv(float* __restrict__ attn) {
    int z = blockIdx.z, b = z >> 3, h = z & 7;
    float* Ab = attn + (size_t)z * L_ * L_;
    const float* Bb = g_V + (size_t)b * L_ * D_ + h * DK_;
    float* Cb = g_O + (size_t)b * L_ * D_ + h * DK_;
    gemm_pipe<true>(Ab, Bb, nullptr, Cb, L_, L_, D_, D_,
                    g_rinv + (size_t)z * L_, Ab);
}

__global__ void __launch_bounds__(NTHR, 2) k_fc(const float* __restrict__ W,
        const float* __restrict__ bias) {
    gemm_big<false>(g_O, W, bias, g_O2, D_, D_, D_, D_);
}
__global__ void __launch_bounds__(NTHR, 2) k_s2(const float* __restrict__ W,
        const float* __restrict__ bias) {
    gemm_big<false>(g_X, W, bias, g_O, D_, D_, D_, D_);
}

// ---------------------------------------------------------------------------
// small epilogues
// ---------------------------------------------------------------------------
__global__ void k_lat(const float* __restrict__ latent, const float* __restrict__ Ws1,
                      const float* __restrict__ bs1) {
    int b = blockIdx.x;
    __shared__ float sl[D_];
    for (int i = threadIdx.x; i < D_; i += 128) {
        float x = latent[b * D_ + i];
        sl[i] = x / (1.0f + __expf(-x));
    }
    __syncthreads();
    int j = blockIdx.y * 128 + threadIdx.x;
    float acc = bs1[j];
    for (int k = 0; k < D_; k++) acc += sl[k] * Ws1[(size_t)k * (2 * D_) + j];
    g_lat[b * (2 * D_) + j] = acc;
}

__global__ void k_film(const float* __restrict__ en_g, const float* __restrict__ en_b) {
    int row = blockIdx.x;
    int b = row >> 10;
    int t = threadIdx.x;
    float4 v = ((const float4*)(g_O2 + (size_t)row * D_))[t];
    __shared__ float red[128];

    red[t] = v.x + v.y + v.z + v.w;
    __syncthreads();
    for (int s = 64; s > 0; s >>= 1) {
        if (t < s) red[t] += red[t + s];
        __syncthreads();
    }
    float mean = red[0] * (1.0f / D_);
    __syncthreads();

    float dx = v.x - mean, dy = v.y - mean, dz = v.z - mean, dw = v.w - mean;
    red[t] = dx * dx + dy * dy + dz * dz + dw * dw;
    __syncthreads();
    for (int s = 64; s > 0; s >>= 1) {
        if (t < s) red[t] += red[t + s];
        __syncthreads();
    }
    float rstd = rsqrtf(red[0] * (1.0f / D_) + 1e-5f);

    int j = t * 4;
    float4 g4 = ((const float4*)en_g)[t];
    float4 b4 = ((const float4*)en_b)[t];
    float4 sc = *(const float4*)(g_lat + b * (2 * D_) + j);
    float4 sh = *(const float4*)(g_lat + b * (2 * D_) + D_ + j);

    float4 o;
    {
        float h;
        h = (dx * rstd * g4.x + b4.x) * (1.0f + sc.x) + sh.x; o.x = h / (1.0f + __expf(-h));
        h = (dy * rstd * g4.y + b4.y) * (1.0f + sc.y) + sh.y; o.y = h / (1.0f + __expf(-h));
        h = (dz * rstd * g4.z + b4.z) * (1.0f + sc.z) + sh.z; o.z = h / (1.0f + __expf(-h));
        h = (dw * rstd * g4.w + b4.w) * (1.0f + sc.w) + sh.w; o.w = h / (1.0f + __expf(-h));
    }
    ((float4*)(g_X + (size_t)row * D_))[t] = o;
}

__global__ void k_final(const float* __restrict__ resid, const float* __restrict__ ln_g,
                        const float* __restrict__ ln_b, float* __restrict__ out) {
    int row = blockIdx.x;
    int t = threadIdx.x;
    float4 v = ((const float4*)(g_O + (size_t)row * D_))[t];
    float4 r = ((const float4*)(resid + (size_t)row * D_))[t];
    v.x += r.x; v.y += r.y; v.z += r.z; v.w += r.w;
    __shared__ float red[128];

    red[t] = v.x + v.y + v.z + v.w;
    __syncthreads();
    for (int s = 64; s > 0; s >>= 1) {
        if (t < s) red[t] += red[t + s];
        __syncthreads();
    }
    float mean = red[0] * (1.0f / D_);
    __syncthreads();

    float dx = v.x - mean, dy = v.y - mean, dz = v.z - mean, dw = v.w - mean;
    red[t] = dx * dx + dy * dy + dz * dz + dw * dw;
    __syncthreads();
    for (int s = 64; s > 0; s >>= 1) {
        if (t < s) red[t] += red[t + s];
        __syncthreads();
    }
    float rstd = rsqrtf(red[0] * (1.0f / D_) + 1e-6f);

    float4 g4 = ((const float4*)ln_g)[t];
    float4 b4 = ((const float4*)ln_b)[t];
    float4 o;
    o.x = dx * rstd * g4.x + b4.x;
    o.y = dy * rstd * g4.y + b4.y;
    o.z = dz * rstd * g4.z + b4.z;
    o.w = dw * rstd * g4.w + b4.w;
    ((float4*)(out + (size_t)row * D_))[t] = o;
}

// ---------------------------------------------------------------------------
extern "C" void kernel_launch(void* const* d_in, const int* in_sizes, int n_in,
                              void* d_out, int out_size) {
    const float* q      = (const float*)d_in[0];
    const float* k      = (const float*)d_in[1];
    const float* v      = (const float*)d_in[2];
    const float* latent = (const float*)d_in[3];
    const float* Wq  = (const float*)d_in[4];
    const float* bq  = (const float*)d_in[5];
    const float* Wk  = (const float*)d_in[6];
    const float* bk  = (const float*)d_in[7];
    const float* Wv  = (const float*)d_in[8];
    const float* bv  = (const float*)d_in[9];
    const float* Wfc = (const float*)d_in[10];
    const float* bfc = (const float*)d_in[11];
    const float* Ws1 = (const float*)d_in[12];
    const float* bs1 = (const float*)d_in[13];
    const float* Ws2 = (const float*)d_in[14];
    const float* bs2 = (const float*)d_in[15];
    const float* en_g = (const float*)d_in[16];
    const float* en_b = (const float*)d_in[17];
    const float* ln_g = (const float*)d_in[18];
    const float* ln_b = (const float*)d_in[19];

    float* out  = (float*)d_out;
    float* attn = out + ATT_OFF;

    cudaFuncSetAttribute(k_proj_qkv, cudaFuncAttributeMaxDynamicSharedMemorySize, SMEM_BIG);
    cudaFuncSetAttribute(k_fc,   cudaFuncAttributeMaxDynamicSharedMemorySize, SMEM_BIG);
    cudaFuncSetAttribute(k_s2,   cudaFuncAttributeMaxDynamicSharedMemorySize, SMEM_BIG);
    cudaFuncSetAttribute(k_scores, cudaFuncAttributeMaxDynamicSharedMemorySize, SMEM_SC);
    cudaFuncSetAttribute(k_attnv, cudaFuncAttributeMaxDynamicSharedMemorySize, SMEM_GEMM);

    dim3 t256(NTHR);
    dim3 gBig(D_ / 128, BL_ / 128);         // (4, 64)

    k_proj_qkv<<<dim3(D_ / 128, BL_ / 128, 3), t256, SMEM_BIG>>>(
        q, k, v, Wq, Wk, Wv, bq, bk, bv);

    k_scores<<<dim3(L_ / 64, L_ / 128, B_ * H_), t256, SMEM_SC>>>(attn);
    k_rowsum<<<(B_ * H_ * L_) / 256, 256>>>();
    k_attnv<<<dim3(1, L_ / BM, B_ * H_), t256, SMEM_GEMM>>>(attn);

    k_fc<<<gBig, t256, SMEM_BIG>>>(Wfc, bfc);
    k_lat<<<dim3(B_, 8), 128>>>(latent, Ws1, bs1);
    k_film<<<BL_, 128>>>(en_g, en_b);
    k_s2<<<gBig, t256, SMEM_BIG>>>(Ws2, bs2);
    k_final<<<BL_, 128>>>(q, ln_g, ln_b, out);
}

// round 11
// speedup vs baseline: 1.1327x; 1.0092x over previous
#include <cuda_runtime.h>
#include <cstdint>

// Problem dims
#define B_ 8
#define L_ 1024
#define D_ 512
#define H_ 8
#define DK_ 64
#define BL_ (B_ * L_)               // 8192
#define ATT_OFF ((size_t)BL_ * D_)  // start of attn in d_out

#define NTHR 256

// attnv tile (64x64)
#define AV_ASZ (64 * 36)
#define AV_BSZ (32 * 72)
#define SMEM_AV ((2 * AV_ASZ + 2 * AV_BSZ + 64) * 4)     // 37,120 B

// big GEMM tile (128x128)
#define ABZ (128 * 36)
#define BBZ (32 * 136)
#define SMEM_BIG ((2 * ABZ + 2 * BBZ + 32) * 4)          // 71808 B

#define SMEM_SC   ((128 * 68 + 64 * 68 + 256) * 4)       // scores

// Scratch (static device globals — no allocation)
__device__ float g_Q[BL_ * D_];
__device__ float g_K[BL_ * D_];
__device__ float g_V[BL_ * D_];
__device__ float g_O[BL_ * D_];
__device__ float g_O2[BL_ * D_];
__device__ float g_X[BL_ * D_];
__device__ float g_lat[B_ * 2 * D_];
__device__ float g_psum[(size_t)B_ * H_ * 16 * L_];

// ---------------------------------------------------------------------------
// helpers
// ---------------------------------------------------------------------------
__device__ __forceinline__ float tf32r(float x) {
    uint32_t o;
    asm("cvt.rna.tf32.f32 %0, %1;" : "=r"(o) : "f"(x));
    return __uint_as_float(o);
}

__device__ __forceinline__ void mma_tf32(float c[4], const float a[4], const float b[2]) {
    asm volatile(
        "mma.sync.aligned.m16n8k8.row.col.f32.tf32.tf32.f32 "
        "{%0,%1,%2,%3}, {%4,%5,%6,%7}, {%8,%9}, {%0,%1,%2,%3};"
        : "+f"(c[0]), "+f"(c[1]), "+f"(c[2]), "+f"(c[3])
        : "r"(__float_as_uint(a[0])), "r"(__float_as_uint(a[1])),
          "r"(__float_as_uint(a[2])), "r"(__float_as_uint(a[3])),
          "r"(__float_as_uint(b[0])), "r"(__float_as_uint(b[1])));
}

__device__ __forceinline__ void cp16(float* dst_smem, const float* src) {
    uint32_t d = (uint32_t)__cvta_generic_to_shared(dst_smem);
    asm volatile("cp.async.cg.shared.global [%0], [%1], 16;" :: "r"(d), "l"(src));
}
#define CP_COMMIT() asm volatile("cp.async.commit_group;")
#define CP_WAIT0()  asm volatile("cp.async.wait_group 0;")
#define CP_WAIT1()  asm volatile("cp.async.wait_group 1;")

// ---------------------------------------------------------------------------
// attnv: O = (E @ V) * rinv, writing normalized attn back as E streams
// through. 64x64 tile, 2-stage cp.async, rinv computed inline from psums.
// grid (16 rowtiles, 64 heads), 256 threads.
// ---------------------------------------------------------------------------
__global__ void __launch_bounds__(NTHR) k_attnv(float* __restrict__ attn) {
    extern __shared__ float sm[];
    float* Asm = sm;                    // [2][64][36]
    float* Bsm = sm + 2 * AV_ASZ;       // [2][32][72]
    float* sRinv = Bsm + 2 * AV_BSZ;    // [64]

    const int t = threadIdx.x;
    const int lane = t & 31, w = t >> 5;
    const int wm = w & 3, wn = w >> 2;      // 4(m:16) x 2(n:32)
    const int g = lane >> 2, tg = lane & 3;
    const int z = blockIdx.y, b = z >> 3, h = z & 7;
    const int row0 = blockIdx.x * 64;

    float* Ag = attn + (size_t)z * L_ * L_;                    // E rows
    const float* Bg = g_V + (size_t)b * L_ * D_ + h * DK_;     // V

    // inline rowsum -> rinv
    if (t < 64) {
        float s = 0.f;
        #pragma unroll
        for (int ct = 0; ct < 16; ct++)
            s += g_psum[((size_t)z * 16 + ct) * L_ + row0 + t];
        sRinv[t] = 1.0f / s;
    }

    float acc[4][4] = {};

    {
        #pragma unroll
        for (int i = 0; i < 2; i++) {
            int idx = t + i * NTHR, r = idx >> 3, c4 = (idx & 7) << 2;
            cp16(Asm + r * 36 + c4, Ag + (size_t)(row0 + r) * L_ + c4);
        }
        #pragma unroll
        for (int i = 0; i < 2; i++) {
            int idx = t + i * NTHR, r = idx >> 4, c4 = (idx & 15) << 2;
            cp16(Bsm + r * 72 + c4, Bg + (size_t)r * D_ + c4);
        }
        CP_COMMIT();
    }

    int buf = 0;
    for (int k0 = 0; k0 < L_; k0 += 32) {
        if (k0 + 32 < L_) {
            float* Ad = Asm + (buf ^ 1) * AV_ASZ;
            float* Bd = Bsm + (buf ^ 1) * AV_BSZ;
            int kn = k0 + 32;
            #pragma unroll
            for (int i = 0; i < 2; i++) {
                int idx = t + i * NTHR, r = idx >> 3, c4 = (idx & 7) << 2;
                cp16(Ad + r * 36 + c4, Ag + (size_t)(row0 + r) * L_ + kn + c4);
            }
            #pragma unroll
            for (int i = 0; i < 2; i++) {
                int idx = t + i * NTHR, r = idx >> 4, c4 = (idx & 15) << 2;
                cp16(Bd + r * 72 + c4, Bg + (size_t)(kn + r) * D_ + c4);
            }
            CP_COMMIT();
            CP_WAIT1();
        } else {
            CP_WAIT0();
        }
        __syncthreads();

        float* Ab = Asm + buf * AV_ASZ;
        float* Bb = Bsm + buf * AV_BSZ;

        // write normalized attn chunk back (coalesced float4)
        #pragma unroll
        for (int i = 0; i < 2; i++) {
            int idx = t + i * NTHR, r = idx >> 3, c4 = (idx & 7) << 2;
            float4 v = *(const float4*)(Ab + r * 36 + c4);
            float s = sRinv[r];
            v.x *= s; v.y *= s; v.z *= s; v.w *= s;
            *(float4*)(Ag + (size_t)(row0 + r) * L_ + k0 + c4) = v;
        }

        #pragma unroll
        for (int ks = 0; ks < 32; ks += 8) {
            float a[4], bf[4][2];
            {
                int r = wm * 16 + g;
                a[0] = tf32r(Ab[r * 36 + ks + tg]);
                a[1] = tf32r(Ab[(r + 8) * 36 + ks + tg]);
                a[2] = tf32r(Ab[r * 36 + ks + tg + 4]);
                a[3] = tf32r(Ab[(r + 8) * 36 + ks + tg + 4]);
            }
            #pragma unroll
            for (int nt = 0; nt < 4; nt++) {
                int n = wn * 32 + nt * 8 + g;
                bf[nt][0] = Bb[(ks + tg) * 72 + n];
                bf[nt][1] = Bb[(ks + tg + 4) * 72 + n];
            }
            #pragma unroll
            for (int nt = 0; nt < 4; nt++)
                mma_tf32(acc[nt], a, bf[nt]);
        }
        __syncthreads();
        buf ^= 1;
    }

    // epilogue: O rows scaled by rinv
    #pragma unroll
    for (int nt = 0; nt < 4; nt++) {
        int rl = wm * 16 + g;
        int c = wn * 32 + nt * 8 + tg * 2;
        float s0 = sRinv[rl], s1 = sRinv[rl + 8];
        float* Og = g_O + (size_t)(b * L_ + row0 + rl) * D_ + h * DK_ + c;
        *(float2*)Og = make_float2(acc[nt][0] * s0, acc[nt][1] * s0);
        *(float2*)(Og + 8 * D_) = make_float2(acc[nt][2] * s1, acc[nt][3] * s1);
    }
}

// ---------------------------------------------------------------------------
// 128x128 double-buffered GEMM (projections / fc / s2). Warp tile 32x64.
// RND: round C to tf32 on store (Q/K/V so downstream skips cvt).
// ---------------------------------------------------------------------------
template <bool RND>
__device__ __forceinline__ void gemm_big(
    const float* __restrict__ A, const float* __restrict__ Bg,
    const float* __restrict__ bias, float* __restrict__ C,
    int K, int lda, int ldb, int ldc)
{
    extern __shared__ float sm[];
    float* Asm = sm;                    // [2][128][36]
    float* Bsm = sm + 2 * ABZ;          // [2][32][136]

    const int t = threadIdx.x;
    const int lane = t & 31, w = t >> 5;
    const int wm = w & 3, wn = w >> 2;          // 4(m) x 2(n)
    const int g = lane >> 2, tg = lane & 3;
    const int row0 = blockIdx.y * 128;
    const int col0 = blockIdx.x * 128;

    float acc[2][8][4] = {};

    {
        #pragma unroll
        for (int i = 0; i < 4; i++) {
            int idx = t + i * NTHR, r = idx >> 3, c4 = (idx & 7) << 2;
            cp16(Asm + r * 36 + c4, A + (size_t)(row0 + r) * lda + c4);
        }
        #pragma unroll
        for (int i = 0; i < 4; i++) {
            int idx = t + i * NTHR, r = idx >> 5, c4 = (idx & 31) << 2;
            cp16(Bsm + r * 136 + c4, Bg + (size_t)r * ldb + col0 + c4);
        }
        CP_COMMIT();
    }

    int buf = 0;
    for (int k0 = 0; k0 < K; k0 += 32) {
        if (k0 + 32 < K) {
            float* Ad = Asm + (buf ^ 1) * ABZ;
            float* Bd = Bsm + (buf ^ 1) * BBZ;
            int kn = k0 + 32;
            #pragma unroll
            for (int i = 0; i < 4; i++) {
                int idx = t + i * NTHR, r = idx >> 3, c4 = (idx & 7) << 2;
                cp16(Ad + r * 36 + c4, A + (size_t)(row0 + r) * lda + kn + c4);
            }
            #pragma unroll
            for (int i = 0; i < 4; i++) {
                int idx = t + i * NTHR, r = idx >> 5, c4 = (idx & 31) << 2;
                cp16(Bd + r * 136 + c4, Bg + (size_t)(kn + r) * ldb + col0 + c4);
            }
            CP_COMMIT();
            CP_WAIT1();
        } else {
            CP_WAIT0();
        }
        __syncthreads();

        float* Ab = Asm + buf * ABZ;
        float* Bb = Bsm + buf * BBZ;

        #pragma unroll
        for (int ks = 0; ks < 32; ks += 8) {
            float a[2][4], bf[8][2];
            #pragma unroll
            for (int mt = 0; mt < 2; mt++) {
                int r = wm * 32 + mt * 16 + g;
                a[mt][0] = tf32r(Ab[r * 36 + ks + tg]);
                a[mt][1] = tf32r(Ab[(r + 8) * 36 + ks + tg]);
                a[mt][2] = tf32r(Ab[r * 36 + ks + tg + 4]);
                a[mt][3] = tf32r(Ab[(r + 8) * 36 + ks + tg + 4]);
            }
            #pragma unroll
            for (int nt = 0; nt < 8; nt++) {
                int n = wn * 64 + nt * 8 + g;
                bf[nt][0] = tf32r(Bb[(ks + tg) * 136 + n]);
                bf[nt][1] = tf32r(Bb[(ks + tg + 4) * 136 + n]);
            }
            #pragma unroll
            for (int mt = 0; mt < 2; mt++)
                #pragma unroll
                for (int nt = 0; nt < 8; nt++)
                    mma_tf32(acc[mt][nt], a[mt], bf[nt]);
        }
        __syncthreads();
        buf ^= 1;
    }

    #pragma unroll
    for (int mt = 0; mt < 2; mt++) {
        #pragma unroll
        for (int nt = 0; nt < 8; nt++) {
            int r = row0 + wm * 32 + mt * 16 + g;
            int c = col0 + wn * 64 + nt * 8 + tg * 2;
            float b0 = 0.f, b1 = 0.f;
            if (bias) { b0 = bias[c]; b1 = bias[c + 1]; }
            float o0 = acc[mt][nt][0] + b0, o1 = acc[mt][nt][1] + b1;
            float o2 = acc[mt][nt][2] + b0, o3 = acc[mt][nt][3] + b1;
            if (RND) { o0 = tf32r(o0); o1 = tf32r(o1); o2 = tf32r(o2); o3 = tf32r(o3); }
            *(float2*)(C + (size_t)r * ldc + c) = make_float2(o0, o1);
            *(float2*)(C + (size_t)(r + 8) * ldc + c) = make_float2(o2, o3);
        }
    }
}

// ---------------------------------------------------------------------------
// scores: E = exp(QK^T/8), staged coalesced write + partial row sums.
// grid (16 coltiles, 8 rowtiles, 64 heads). Q/K pre-rounded (no cvt).
// ---------------------------------------------------------------------------
__global__ void __launch_bounds__(256) k_scores(float* __restrict__ attn) {
    extern __shared__ float sm[];
    float* Qs = sm;                     // [128][68], reused to stage E
    float* Ks = sm + 128 * 68;          // [64][68]
    float* sPart = Ks + 64 * 68;        // [2][128]

    const int t = threadIdx.x;
    const int lane = t & 31, w = t >> 5;
    const int wm = w & 3, wn = w >> 2;
    const int g = lane >> 2, tg = lane & 3;
    const int z = blockIdx.z, b = z >> 3, h = z & 7;
    const int row0 = blockIdx.y * 128;
    const int col0 = blockIdx.x * 64;

    const float* Qg = g_Q + (size_t)b * L_ * D_ + h * DK_;
    const float* Kg = g_K + (size_t)b * L_ * D_ + h * DK_;
    float* attn_b = attn + (size_t)z * L_ * L_;

    #pragma unroll
    for (int i = 0; i < 8; i++) {
        int idx = t + i * 256, r = idx >> 4, c4 = (idx & 15) << 2;
        cp16(Qs + r * 68 + c4, Qg + (size_t)(row0 + r) * D_ + c4);
    }
    #pragma unroll
    for (int i = 0; i < 4; i++) {
        int idx = t + i * 256, r = idx >> 4, c4 = (idx & 15) << 2;
        cp16(Ks + r * 68 + c4, Kg + (size_t)(col0 + r) * D_ + c4);
    }
    CP_COMMIT();
    CP_WAIT0();
    __syncthreads();

    float acc[2][4][4] = {};
    #pragma unroll
    for (int ks = 0; ks < DK_; ks += 8) {
        float a[2][4], bf[4][2];
        #pragma unroll
        for (int mt = 0; mt < 2; mt++) {
            int r = wm * 32 + mt * 16 + g;
            a[mt][0] = Qs[r * 68 + ks + tg];
            a[mt][1] = Qs[(r + 8) * 68 + ks + tg];
            a[mt][2] = Qs[r * 68 + ks + tg + 4];
            a[mt][3] = Qs[(r + 8) * 68 + ks + tg + 4];
        }
        #pragma unroll
        for (int nt = 0; nt < 4; nt++) {
            int n = wn * 32 + nt * 8 + g;
            bf[nt][0] = Ks[n * 68 + ks + tg];
            bf[nt][1] = Ks[n * 68 + ks + tg + 4];
        }
        #pragma unroll
        for (int mt = 0; mt < 2; mt++)
            #pragma unroll
            for (int nt = 0; nt < 4; nt++)
                mma_tf32(acc[mt][nt], a[mt], bf[nt]);
    }
    __syncthreads();    // all warps done reading Qs; reuse it as staging

    // exp epilogue: stage E into Qs, accumulate partial row sums
    float rs[2][2] = {};
    #pragma unroll
    for (int mt = 0; mt < 2; mt++) {
        int rl = wm * 32 + mt * 16 + g;
        #pragma unroll
        for (int nt = 0; nt < 4; nt++) {
            int c = wn * 32 + nt * 8 + tg * 2;
            float e0 = __expf(acc[mt][nt][0] * 0.125f);
            float e1 = __expf(acc[mt][nt][1] * 0.125f);
            float e2 = __expf(acc[mt][nt][2] * 0.125f);
            float e3 = __expf(acc[mt][nt][3] * 0.125f);
            Qs[rl * 68 + c]           = e0;
            Qs[rl * 68 + c + 1]       = e1;
            Qs[(rl + 8) * 68 + c]     = e2;
            Qs[(rl + 8) * 68 + c + 1] = e3;
            rs[mt][0] += e0 + e1;
            rs[mt][1] += e2 + e3;
        }
    }
    #pragma unroll
    for (int mt = 0; mt < 2; mt++) {
        #pragma unroll
        for (int j = 0; j < 2; j++) {
            rs[mt][j] += __shfl_xor_sync(~0u, rs[mt][j], 1);
            rs[mt][j] += __shfl_xor_sync(~0u, rs[mt][j], 2);
        }
        if (tg == 0) {
            int rl = wm * 32 + mt * 16 + g;
            sPart[wn * 128 + rl] = rs[mt][0];
            sPart[wn * 128 + rl + 8] = rs[mt][1];
        }
    }
    __syncthreads();

    // coalesced write: 128 rows x 64 cols of E
    #pragma unroll
    for (int i = 0; i < 8; i++) {
        int idx = t + i * 256, r = idx >> 4, c4 = (idx & 15) << 2;
        *(float4*)(attn_b + (size_t)(row0 + r) * L_ + col0 + c4) =
            *(const float4*)(Qs + r * 68 + c4);
    }
    if (t < 128)
        g_psum[((size_t)z * 16 + blockIdx.x) * L_ + row0 + t] =
            sPart[t] + sPart[128 + t];
}

// ---------------------------------------------------------------------------
// GEMM wrappers
// ---------------------------------------------------------------------------
__global__ void __launch_bounds__(NTHR, 2) k_proj_qkv(
        const float* __restrict__ q, const float* __restrict__ k,
        const float* __restrict__ v,
        const float* __restrict__ Wq, const float* __restrict__ Wk,
        const float* __restrict__ Wv,
        const float* __restrict__ bq, const float* __restrict__ bk,
        const float* __restrict__ bv) {
    int z = blockIdx.z;
    const float* A = (z == 0) ? q : (z == 1) ? k : v;
    const float* W = (z == 0) ? Wq : (z == 1) ? Wk : Wv;
    const float* bias = (z == 0) ? bq : (z == 1) ? bk : bv;
    float* C = (z == 0) ? g_Q : (z == 1) ? g_K : g_V;
    gemm_big<true>(A, W, bias, C, D_, D_, D_, D_);
}

__global__ void __launch_bounds__(NTHR, 2) k_fc(const float* __restrict__ W,
        const float* __restrict__ bias) {
    gemm_big<false>(g_O, W, bias, g_O2, D_, D_, D_, D_);
}
__global__ void __launch_bounds__(NTHR, 2) k_s2(const float* __restrict__ W,
        const float* __restrict__ bias) {
    gemm_big<false>(g_X, W, bias, g_O, D_, D_, D_, D_);
}

// ---------------------------------------------------------------------------
// small epilogues
// ---------------------------------------------------------------------------
__global__ void k_lat(const float* __restrict__ latent, const float* __restrict__ Ws1,
                      const float* __restrict__ bs1) {
    int b = blockIdx.x;
    __shared__ float sl[D_];
    for (int i = threadIdx.x; i < D_; i += 128) {
        float x = latent[b * D_ + i];
        sl[i] = x / (1.0f + __expf(-x));
    }
    __syncthreads();
    int j = blockIdx.y * 128 + threadIdx.x;
    float acc = bs1[j];
    for (int k = 0; k < D_; k++) acc += sl[k] * Ws1[(size_t)k * (2 * D_) + j];
    g_lat[b * (2 * D_) + j] = acc;
}

__global__ void k_film(const float* __restrict__ en_g, const float* __restrict__ en_b) {
    int row = blockIdx.x;
    int b = row >> 10;
    int t = threadIdx.x;
    float4 v = ((const float4*)(g_O2 + (size_t)row * D_))[t];
    __shared__ float red[128];

    red[t] = v.x + v.y + v.z + v.w;
    __syncthreads();
    for (int s = 64; s > 0; s >>= 1) {
        if (t < s) red[t] += red[t + s];
        __syncthreads();
    }
    float mean = red[0] * (1.0f / D_);
    __syncthreads();

    float dx = v.x - mean, dy = v.y - mean, dz = v.z - mean, dw = v.w - mean;
    red[t] = dx * dx + dy * dy + dz * dz + dw * dw;
    __syncthreads();
    for (int s = 64; s > 0; s >>= 1) {
        if (t < s) red[t] += red[t + s];
        __syncthreads();
    }
    float rstd = rsqrtf(red[0] * (1.0f / D_) + 1e-5f);

    int j = t * 4;
    float4 g4 = ((const float4*)en_g)[t];
    float4 b4 = ((const float4*)en_b)[t];
    float4 sc = *(const float4*)(g_lat + b * (2 * D_) + j);
    float4 sh = *(const float4*)(g_lat + b * (2 * D_) + D_ + j);

    float4 o;
    {
        float h;
        h = (dx * rstd * g4.x + b4.x) * (1.0f + sc.x) + sh.x; o.x = h / (1.0f + __expf(-h));
        h = (dy * rstd * g4.y + b4.y) * (1.0f + sc.y) + sh.y; o.y = h / (1.0f + __expf(-h));
        h = (dz * rstd * g4.z + b4.z) * (1.0f + sc.z) + sh.z; o.z = h / (1.0f + __expf(-h));
        h = (dw * rstd * g4.w + b4.w) * (1.0f + sc.w) + sh.w; o.w = h / (1.0f + __expf(-h));
    }
    ((float4*)(g_X + (size_t)row * D_))[t] = o;
}

__global__ void k_final(const float* __restrict__ resid, const float* __restrict__ ln_g,
                        const float* __restrict__ ln_b, float* __restrict__ out) {
    int row = blockIdx.x;
    int t = threadIdx.x;
    float4 v = ((const float4*)(g_O + (size_t)row * D_))[t];
    float4 r = ((const float4*)(resid + (size_t)row * D_))[t];
    v.x += r.x; v.y += r.y; v.z += r.z; v.w += r.w;
    __shared__ float red[128];

    red[t] = v.x + v.y + v.z + v.w;
    __syncthreads();
    for (int s = 64; s > 0; s >>= 1) {
        if (t < s) red[t] += red[t + s];
        __syncthreads();
    }
    float mean = red[0] * (1.0f / D_);
    __syncthreads();

    float dx = v.x - mean, dy = v.y - mean, dz = v.z - mean, dw = v.w - mean;
    red[t] = dx * dx + dy * dy + dz * dz + dw * dw;
    __syncthreads();
    for (int s = 64; s > 0; s >>= 1) {
        if (t < s) red[t] += red[t + s];
        __syncthreads();
    }
    float rstd = rsqrtf(red[0] * (1.0f / D_) + 1e-6f);

    float4 g4 = ((const float4*)ln_g)[t];
    float4 b4 = ((const float4*)ln_b)[t];
    float4 o;
    o.x = dx * rstd * g4.x + b4.x;
    o.y = dy * rstd * g4.y + b4.y;
    o.z = dz * rstd * g4.z + b4.z;
    o.w = dw * rstd * g4.w + b4.w;
    ((float4*)(out + (size_t)row * D_))[t] = o;
}

// ---------------------------------------------------------------------------
extern "C" void kernel_launch(void* const* d_in, const int* in_sizes, int n_in,
                              void* d_out, int out_size) {
    const float* q      = (const float*)d_in[0];
    const float* k      = (const float*)d_in[1];
    const float* v      = (const float*)d_in[2];
    const float* latent = (const float*)d_in[3];
    const float* Wq  = (const float*)d_in[4];
    const float* bq  = (const float*)d_in[5];
    const float* Wk  = (const float*)d_in[6];
    const float* bk  = (const float*)d_in[7];
    const float* Wv  = (const float*)d_in[8];
    const float* bv  = (const float*)d_in[9];
    const float* Wfc = (const float*)d_in[10];
    const float* bfc = (const float*)d_in[11];
    const float* Ws1 = (const float*)d_in[12];
    const float* bs1 = (const float*)d_in[13];
    const float* Ws2 = (const float*)d_in[14];
    const float* bs2 = (const float*)d_in[15];
    const float* en_g = (const float*)d_in[16];
    const float* en_b = (const float*)d_in[17];
    const float* ln_g = (const float*)d_in[18];
    const float* ln_b = (const float*)d_in[19];

    float* out  = (float*)d_out;
    float* attn = out + ATT_OFF;

    cudaFuncSetAttribute(k_proj_qkv, cudaFuncAttributeMaxDynamicSharedMemorySize, SMEM_BIG);
    cudaFuncSetAttribute(k_fc,   cudaFuncAttributeMaxDynamicSharedMemorySize, SMEM_BIG);
    cudaFuncSetAttribute(k_s2,   cudaFuncAttributeMaxDynamicSharedMemorySize, SMEM_BIG);
    cudaFuncSetAttribute(k_scores, cudaFuncAttributeMaxDynamicSharedMemorySize, SMEM_SC);
    cudaFuncSetAttribute(k_attnv, cudaFuncAttributeMaxDynamicSharedMemorySize, SMEM_AV);

    dim3 t256(NTHR);
    dim3 gBig(D_ / 128, BL_ / 128);         // (4, 64)

    k_proj_qkv<<<dim3(D_ / 128, BL_ / 128, 3), t256, SMEM_BIG>>>(
        q, k, v, Wq, Wk, Wv, bq, bk, bv);

    k_scores<<<dim3(L_ / 64, L_ / 128, B_ * H_), t256, SMEM_SC>>>(attn);
    k_attnv<<<dim3(L_ / 64, B_ * H_), t256, SMEM_AV>>>(attn);

    k_fc<<<gBig, t256, SMEM_BIG>>>(Wfc, bfc);
    k_lat<<<dim3(B_, 8), 128>>>(latent, Ws1, bs1);
    k_film<<<BL_, 128>>>(en_g, en_b);
    k_s2<<<gBig, t256, SMEM_BIG>>>(Ws2, bs2);
    k_final<<<BL_, 128>>>(q, ln_g, ln_b, out);
}

// round 12
// speedup vs baseline: 1.1489x; 1.0142x over previous
#include <cuda_runtime.h>
#include <cstdint>

// Problem dims
#define B_ 8
#define L_ 1024
#define D_ 512
#define H_ 8
#define DK_ 64
#define BL_ (B_ * L_)               // 8192
#define ATT_OFF ((size_t)BL_ * D_)  // start of attn in d_out

#define NTHR 256

// attnv tile (64x64)
#define AV_ASZ (64 * 36)
#define AV_BSZ (32 * 72)
#define SMEM_AV ((2 * AV_ASZ + 2 * AV_BSZ + 64) * 4)     // 37,120 B

// big GEMM tile (128x128)
#define ABZ (128 * 36)
#define BBZ (32 * 136)
#define SMEM_BIG ((2 * ABZ + 2 * BBZ + 32) * 4)          // 71808 B

#define SMEM_SC   ((128 * 68 + 64 * 68 + 256) * 4)       // scores

// Scratch (static device globals — no allocation)
__device__ float g_Q[BL_ * D_];
__device__ float g_K[BL_ * D_];
__device__ float g_V[BL_ * D_];
__device__ float g_O[BL_ * D_];
__device__ float g_O2[BL_ * D_];
__device__ float g_X[BL_ * D_];
__device__ float g_lat[B_ * 2 * D_];
__device__ float g_psum[(size_t)B_ * H_ * 16 * L_];
__device__ float g_W[5][D_ * D_];    // tf32-rounded Wq,Wk,Wv,Wfc,Ws2

// ---------------------------------------------------------------------------
// helpers
// ---------------------------------------------------------------------------
__device__ __forceinline__ float tf32r(float x) {
    uint32_t o;
    asm("cvt.rna.tf32.f32 %0, %1;" : "=r"(o) : "f"(x));
    return __uint_as_float(o);
}

__device__ __forceinline__ void mma_tf32(float c[4], const float a[4], const float b[2]) {
    asm volatile(
        "mma.sync.aligned.m16n8k8.row.col.f32.tf32.tf32.f32 "
        "{%0,%1,%2,%3}, {%4,%5,%6,%7}, {%8,%9}, {%0,%1,%2,%3};"
        : "+f"(c[0]), "+f"(c[1]), "+f"(c[2]), "+f"(c[3])
        : "r"(__float_as_uint(a[0])), "r"(__float_as_uint(a[1])),
          "r"(__float_as_uint(a[2])), "r"(__float_as_uint(a[3])),
          "r"(__float_as_uint(b[0])), "r"(__float_as_uint(b[1])));
}

__device__ __forceinline__ void cp16(float* dst_smem, const float* src) {
    uint32_t d = (uint32_t)__cvta_generic_to_shared(dst_smem);
    asm volatile("cp.async.cg.shared.global [%0], [%1], 16;" :: "r"(d), "l"(src));
}
#define CP_COMMIT() asm volatile("cp.async.commit_group;")
#define CP_WAIT0()  asm volatile("cp.async.wait_group 0;")
#define CP_WAIT1()  asm volatile("cp.async.wait_group 1;")

// ---------------------------------------------------------------------------
// weight pre-round: g_W[m] = tf32r(W_m). grid (256, 5), 256 thr.
// ---------------------------------------------------------------------------
__global__ void k_round(const float* __restrict__ w0, const float* __restrict__ w1,
                        const float* __restrict__ w2, const float* __restrict__ w3,
                        const float* __restrict__ w4) {
    const float* srcs[5] = {w0, w1, w2, w3, w4};
    int m = blockIdx.y;
    int i = (blockIdx.x * 256 + threadIdx.x) * 4;
    float4 v = *(const float4*)(srcs[m] + i);
    v.x = tf32r(v.x); v.y = tf32r(v.y); v.z = tf32r(v.z); v.w = tf32r(v.w);
    *(float4*)(&g_W[m][i]) = v;
}

// ---------------------------------------------------------------------------
// attnv: O = (E @ V) * rinv, writing normalized attn back as E streams
// through. 64x64 tile, 2-stage cp.async, rinv computed inline from psums.
// O stored tf32-rounded (fc consumes without cvt).
// ---------------------------------------------------------------------------
__global__ void __launch_bounds__(NTHR) k_attnv(float* __restrict__ attn) {
    extern __shared__ float sm[];
    float* Asm = sm;                    // [2][64][36]
    float* Bsm = sm + 2 * AV_ASZ;       // [2][32][72]
    float* sRinv = Bsm + 2 * AV_BSZ;    // [64]

    const int t = threadIdx.x;
    const int lane = t & 31, w = t >> 5;
    const int wm = w & 3, wn = w >> 2;      // 4(m:16) x 2(n:32)
    const int g = lane >> 2, tg = lane & 3;
    const int z = blockIdx.y, b = z >> 3, h = z & 7;
    const int row0 = blockIdx.x * 64;

    float* Ag = attn + (size_t)z * L_ * L_;                    // E rows
    const float* Bg = g_V + (size_t)b * L_ * D_ + h * DK_;     // V

    if (t < 64) {
        float s = 0.f;
        #pragma unroll
        for (int ct = 0; ct < 16; ct++)
            s += g_psum[((size_t)z * 16 + ct) * L_ + row0 + t];
        sRinv[t] = 1.0f / s;
    }

    float acc[4][4] = {};

    {
        #pragma unroll
        for (int i = 0; i < 2; i++) {
            int idx = t + i * NTHR, r = idx >> 3, c4 = (idx & 7) << 2;
            cp16(Asm + r * 36 + c4, Ag + (size_t)(row0 + r) * L_ + c4);
        }
        #pragma unroll
        for (int i = 0; i < 2; i++) {
            int idx = t + i * NTHR, r = idx >> 4, c4 = (idx & 15) << 2;
            cp16(Bsm + r * 72 + c4, Bg + (size_t)r * D_ + c4);
        }
        CP_COMMIT();
    }

    int buf = 0;
    for (int k0 = 0; k0 < L_; k0 += 32) {
        if (k0 + 32 < L_) {
            float* Ad = Asm + (buf ^ 1) * AV_ASZ;
            float* Bd = Bsm + (buf ^ 1) * AV_BSZ;
            int kn = k0 + 32;
            #pragma unroll
            for (int i = 0; i < 2; i++) {
                int idx = t + i * NTHR, r = idx >> 3, c4 = (idx & 7) << 2;
                cp16(Ad + r * 36 + c4, Ag + (size_t)(row0 + r) * L_ + kn + c4);
            }
            #pragma unroll
            for (int i = 0; i < 2; i++) {
                int idx = t + i * NTHR, r = idx >> 4, c4 = (idx & 15) << 2;
                cp16(Bd + r * 72 + c4, Bg + (size_t)(kn + r) * D_ + c4);
            }
            CP_COMMIT();
            CP_WAIT1();
        } else {
            CP_WAIT0();
        }
        __syncthreads();

        float* Ab = Asm + buf * AV_ASZ;
        float* Bb = Bsm + buf * AV_BSZ;

        // write normalized attn chunk back (coalesced float4)
        #pragma unroll
        for (int i = 0; i < 2; i++) {
            int idx = t + i * NTHR, r = idx >> 3, c4 = (idx & 7) << 2;
            float4 v = *(const float4*)(Ab + r * 36 + c4);
            float s = sRinv[r];
            v.x *= s; v.y *= s; v.z *= s; v.w *= s;
            *(float4*)(Ag + (size_t)(row0 + r) * L_ + k0 + c4) = v;
        }

        #pragma unroll
        for (int ks = 0; ks < 32; ks += 8) {
            float a[4], bf[4][2];
            {
                int r = wm * 16 + g;
                a[0] = tf32r(Ab[r * 36 + ks + tg]);
                a[1] = tf32r(Ab[(r + 8) * 36 + ks + tg]);
                a[2] = tf32r(Ab[r * 36 + ks + tg + 4]);
                a[3] = tf32r(Ab[(r + 8) * 36 + ks + tg + 4]);
            }
            #pragma unroll
            for (int nt = 0; nt < 4; nt++) {
                int n = wn * 32 + nt * 8 + g;
                bf[nt][0] = Bb[(ks + tg) * 72 + n];
                bf[nt][1] = Bb[(ks + tg + 4) * 72 + n];
            }
            #pragma unroll
            for (int nt = 0; nt < 4; nt++)
                mma_tf32(acc[nt], a, bf[nt]);
        }
        __syncthreads();
        buf ^= 1;
    }

    // epilogue: O rows scaled by rinv, tf32-rounded for fc
    #pragma unroll
    for (int nt = 0; nt < 4; nt++) {
        int rl = wm * 16 + g;
        int c = wn * 32 + nt * 8 + tg * 2;
        float s0 = sRinv[rl], s1 = sRinv[rl + 8];
        float* Og = g_O + (size_t)(b * L_ + row0 + rl) * D_ + h * DK_ + c;
        *(float2*)Og = make_float2(tf32r(acc[nt][0] * s0), tf32r(acc[nt][1] * s0));
        *(float2*)(Og + 8 * D_) =
            make_float2(tf32r(acc[nt][2] * s1), tf32r(acc[nt][3] * s1));
    }
}

// ---------------------------------------------------------------------------
// 128x128 double-buffered GEMM. Warp tile 32x64.
// ACVT: cvt A fragments (raw external inputs). B is always pre-rounded.
// RND: round C to tf32 on store.
// ---------------------------------------------------------------------------
template <bool ACVT, bool RND>
__device__ __forceinline__ void gemm_big(
    const float* __restrict__ A, const float* __restrict__ Bg,
    const float* __restrict__ bias, float* __restrict__ C,
    int K, int lda, int ldb, int ldc)
{
    extern __shared__ float sm[];
    float* Asm = sm;                    // [2][128][36]
    float* Bsm = sm + 2 * ABZ;          // [2][32][136]

    const int t = threadIdx.x;
    const int lane = t & 31, w = t >> 5;
    const int wm = w & 3, wn = w >> 2;          // 4(m) x 2(n)
    const int g = lane >> 2, tg = lane & 3;
    const int row0 = blockIdx.y * 128;
    const int col0 = blockIdx.x * 128;

    float acc[2][8][4] = {};

    {
        #pragma unroll
        for (int i = 0; i < 4; i++) {
            int idx = t + i * NTHR, r = idx >> 3, c4 = (idx & 7) << 2;
            cp16(Asm + r * 36 + c4, A + (size_t)(row0 + r) * lda + c4);
        }
        #pragma unroll
        for (int i = 0; i < 4; i++) {
            int idx = t + i * NTHR, r = idx >> 5, c4 = (idx & 31) << 2;
            cp16(Bsm + r * 136 + c4, Bg + (size_t)r * ldb + col0 + c4);
        }
        CP_COMMIT();
    }

    int buf = 0;
    for (int k0 = 0; k0 < K; k0 += 32) {
        if (k0 + 32 < K) {
            float* Ad = Asm + (buf ^ 1) * ABZ;
            float* Bd = Bsm + (buf ^ 1) * BBZ;
            int kn = k0 + 32;
            #pragma unroll
            for (int i = 0; i < 4; i++) {
                int idx = t + i * NTHR, r = idx >> 3, c4 = (idx & 7) << 2;
                cp16(Ad + r * 36 + c4, A + (size_t)(row0 + r) * lda + kn + c4);
            }
            #pragma unroll
            for (int i = 0; i < 4; i++) {
                int idx = t + i * NTHR, r = idx >> 5, c4 = (idx & 31) << 2;
                cp16(Bd + r * 136 + c4, Bg + (size_t)(kn + r) * ldb + col0 + c4);
            }
            CP_COMMIT();
            CP_WAIT1();
        } else {
            CP_WAIT0();
        }
        __syncthreads();

        float* Ab = Asm + buf * ABZ;
        float* Bb = Bsm + buf * BBZ;

        #pragma unroll
        for (int ks = 0; ks < 32; ks += 8) {
            float a[2][4], bf[8][2];
            #pragma unroll
            for (int mt = 0; mt < 2; mt++) {
                int r = wm * 32 + mt * 16 + g;
                if (ACVT) {
                    a[mt][0] = tf32r(Ab[r * 36 + ks + tg]);
                    a[mt][1] = tf32r(Ab[(r + 8) * 36 + ks + tg]);
                    a[mt][2] = tf32r(Ab[r * 36 + ks + tg + 4]);
                    a[mt][3] = tf32r(Ab[(r + 8) * 36 + ks + tg + 4]);
                } else {
                    a[mt][0] = Ab[r * 36 + ks + tg];
                    a[mt][1] = Ab[(r + 8) * 36 + ks + tg];
                    a[mt][2] = Ab[r * 36 + ks + tg + 4];
                    a[mt][3] = Ab[(r + 8) * 36 + ks + tg + 4];
                }
            }
            #pragma unroll
            for (int nt = 0; nt < 8; nt++) {
                int n = wn * 64 + nt * 8 + g;
                bf[nt][0] = Bb[(ks + tg) * 136 + n];
                bf[nt][1] = Bb[(ks + tg + 4) * 136 + n];
            }
            #pragma unroll
            for (int mt = 0; mt < 2; mt++)
                #pragma unroll
                for (int nt = 0; nt < 8; nt++)
                    mma_tf32(acc[mt][nt], a[mt], bf[nt]);
        }
        __syncthreads();
        buf ^= 1;
    }

    #pragma unroll
    for (int mt = 0; mt < 2; mt++) {
        #pragma unroll
        for (int nt = 0; nt < 8; nt++) {
            int r = row0 + wm * 32 + mt * 16 + g;
            int c = col0 + wn * 64 + nt * 8 + tg * 2;
            float b0 = 0.f, b1 = 0.f;
            if (bias) { b0 = bias[c]; b1 = bias[c + 1]; }
            float o0 = acc[mt][nt][0] + b0, o1 = acc[mt][nt][1] + b1;
            float o2 = acc[mt][nt][2] + b0, o3 = acc[mt][nt][3] + b1;
            if (RND) { o0 = tf32r(o0); o1 = tf32r(o1); o2 = tf32r(o2); o3 = tf32r(o3); }
            *(float2*)(C + (size_t)r * ldc + c) = make_float2(o0, o1);
            *(float2*)(C + (size_t)(r + 8) * ldc + c) = make_float2(o2, o3);
        }
    }
}

// ---------------------------------------------------------------------------
// scores: E = exp(QK^T/8), staged coalesced write + partial row sums.
// ---------------------------------------------------------------------------
__global__ void __launch_bounds__(256) k_scores(float* __restrict__ attn) {
    extern __shared__ float sm[];
    float* Qs = sm;                     // [128][68], reused to stage E
    float* Ks = sm + 128 * 68;          // [64][68]
    float* sPart = Ks + 64 * 68;        // [2][128]

    const int t = threadIdx.x;
    const int lane = t & 31, w = t >> 5;
    const int wm = w & 3, wn = w >> 2;
    const int g = lane >> 2, tg = lane & 3;
    const int z = blockIdx.z, b = z >> 3, h = z & 7;
    const int row0 = blockIdx.y * 128;
    const int col0 = blockIdx.x * 64;

    const float* Qg = g_Q + (size_t)b * L_ * D_ + h * DK_;
    const float* Kg = g_K + (size_t)b * L_ * D_ + h * DK_;
    float* attn_b = attn + (size_t)z * L_ * L_;

    #pragma unroll
    for (int i = 0; i < 8; i++) {
        int idx = t + i * 256, r = idx >> 4, c4 = (idx & 15) << 2;
        cp16(Qs + r * 68 + c4, Qg + (size_t)(row0 + r) * D_ + c4);
    }
    #pragma unroll
    for (int i = 0; i < 4; i++) {
        int idx = t + i * 256, r = idx >> 4, c4 = (idx & 15) << 2;
        cp16(Ks + r * 68 + c4, Kg + (size_t)(col0 + r) * D_ + c4);
    }
    CP_COMMIT();
    CP_WAIT0();
    __syncthreads();

    float acc[2][4][4] = {};
    #pragma unroll
    for (int ks = 0; ks < DK_; ks += 8) {
        float a[2][4], bf[4][2];
        #pragma unroll
        for (int mt = 0; mt < 2; mt++) {
            int r = wm * 32 + mt * 16 + g;
            a[mt][0] = Qs[r * 68 + ks + tg];
            a[mt][1] = Qs[(r + 8) * 68 + ks + tg];
            a[mt][2] = Qs[r * 68 + ks + tg + 4];
            a[mt][3] = Qs[(r + 8) * 68 + ks + tg + 4];
        }
        #pragma unroll
        for (int nt = 0; nt < 4; nt++) {
            int n = wn * 32 + nt * 8 + g;
            bf[nt][0] = Ks[n * 68 + ks + tg];
            bf[nt][1] = Ks[n * 68 + ks + tg + 4];
        }
        #pragma unroll
        for (int mt = 0; mt < 2; mt++)
            #pragma unroll
            for (int nt = 0; nt < 4; nt++)
                mma_tf32(acc[mt][nt], a[mt], bf[nt]);
    }
    __syncthreads();

    float rs[2][2] = {};
    #pragma unroll
    for (int mt = 0; mt < 2; mt++) {
        int rl = wm * 32 + mt * 16 + g;
        #pragma unroll
        for (int nt = 0; nt < 4; nt++) {
            int c = wn * 32 + nt * 8 + tg * 2;
            float e0 = __expf(acc[mt][nt][0] * 0.125f);
            float e1 = __expf(acc[mt][nt][1] * 0.125f);
            float e2 = __expf(acc[mt][nt][2] * 0.125f);
            float e3 = __expf(acc[mt][nt][3] * 0.125f);
            Qs[rl * 68 + c]           = e0;
            Qs[rl * 68 + c + 1]       = e1;
            Qs[(rl + 8) * 68 + c]     = e2;
            Qs[(rl + 8) * 68 + c + 1] = e3;
            rs[mt][0] += e0 + e1;
            rs[mt][1] += e2 + e3;
        }
    }
    #pragma unroll
    for (int mt = 0; mt < 2; mt++) {
        #pragma unroll
        for (int j = 0; j < 2; j++) {
            rs[mt][j] += __shfl_xor_sync(~0u, rs[mt][j], 1);
            rs[mt][j] += __shfl_xor_sync(~0u, rs[mt][j], 2);
        }
        if (tg == 0) {
            int rl = wm * 32 + mt * 16 + g;
            sPart[wn * 128 + rl] = rs[mt][0];
            sPart[wn * 128 + rl + 8] = rs[mt][1];
        }
    }
    __syncthreads();

    #pragma unroll
    for (int i = 0; i < 8; i++) {
        int idx = t + i * 256, r = idx >> 4, c4 = (idx & 15) << 2;
        *(float4*)(attn_b + (size_t)(row0 + r) * L_ + col0 + c4) =
            *(const float4*)(Qs + r * 68 + c4);
    }
    if (t < 128)
        g_psum[((size_t)z * 16 + blockIdx.x) * L_ + row0 + t] =
            sPart[t] + sPart[128 + t];
}

// ---------------------------------------------------------------------------
// GEMM wrappers
// ---------------------------------------------------------------------------
__global__ void __launch_bounds__(NTHR, 2) k_proj_qkv(
        const float* __restrict__ q, const float* __restrict__ k,
        const float* __restrict__ v,
        const float* __restrict__ bq, const float* __restrict__ bk,
        const float* __restrict__ bv) {
    int z = blockIdx.z;
    const float* A = (z == 0) ? q : (z == 1) ? k : v;
    const float* bias = (z == 0) ? bq : (z == 1) ? bk : bv;
    float* C = (z == 0) ? g_Q : (z == 1) ? g_K : g_V;
    gemm_big<true, true>(A, g_W[z], bias, C, D_, D_, D_, D_);
}

__global__ void __launch_bounds__(NTHR, 2) k_fc(const float* __restrict__ bias) {
    gemm_big<false, false>(g_O, g_W[3], bias, g_O2, D_, D_, D_, D_);
}
__global__ void __launch_bounds__(NTHR, 2) k_s2(const float* __restrict__ bias) {
    gemm_big<false, false>(g_X, g_W[4], bias, g_O, D_, D_, D_, D_);
}

// ---------------------------------------------------------------------------
// small epilogues
// ---------------------------------------------------------------------------
__global__ void k_lat(const float* __restrict__ latent, const float* __restrict__ Ws1,
                      const float* __restrict__ bs1) {
    int b = blockIdx.x;
    __shared__ float sl[D_];
    for (int i = threadIdx.x; i < D_; i += 128) {
        float x = latent[b * D_ + i];
        sl[i] = x / (1.0f + __expf(-x));
    }
    __syncthreads();
    int j = blockIdx.y * 128 + threadIdx.x;
    float acc = bs1[j];
    for (int k = 0; k < D_; k++) acc += sl[k] * Ws1[(size_t)k * (2 * D_) + j];
    g_lat[b * (2 * D_) + j] = acc;
}

// film: X = tf32r(silu(LN(o2)*(1+scale)+shift)) — s2 consumes without cvt
__global__ void k_film(const float* __restrict__ en_g, const float* __restrict__ en_b) {
    int row = blockIdx.x;
    int b = row >> 10;
    int t = threadIdx.x;
    float4 v = ((const float4*)(g_O2 + (size_t)row * D_))[t];
    __shared__ float red[128];

    red[t] = v.x + v.y + v.z + v.w;
    __syncthreads();
    for (int s = 64; s > 0; s >>= 1) {
        if (t < s) red[t] += red[t + s];
        __syncthreads();
    }
    float mean = red[0] * (1.0f / D_);
    __syncthreads();

    float dx = v.x - mean, dy = v.y - mean, dz = v.z - mean, dw = v.w - mean;
    red[t] = dx * dx + dy * dy + dz * dz + dw * dw;
    __syncthreads();
    for (int s = 64; s > 0; s >>= 1) {
        if (t < s) red[t] += red[t + s];
        __syncthreads();
    }
    float rstd = rsqrtf(red[0] * (1.0f / D_) + 1e-5f);

    int j = t * 4;
    float4 g4 = ((const float4*)en_g)[t];
    float4 b4 = ((const float4*)en_b)[t];
    float4 sc = *(const float4*)(g_lat + b * (2 * D_) + j);
    float4 sh = *(const float4*)(g_lat + b * (2 * D_) + D_ + j);

    float4 o;
    {
        float h;
        h = (dx * rstd * g4.x + b4.x) * (1.0f + sc.x) + sh.x; o.x = tf32r(h / (1.0f + __expf(-h)));
        h = (dy * rstd * g4.y + b4.y) * (1.0f + sc.y) + sh.y; o.y = tf32r(h / (1.0f + __expf(-h)));
        h = (dz * rstd * g4.z + b4.z) * (1.0f + sc.z) + sh.z; o.z = tf32r(h / (1.0f + __expf(-h)));
        h = (dw * rstd * g4.w + b4.w) * (1.0f + sc.w) + sh.w; o.w = tf32r(h / (1.0f + __expf(-h)));
    }
    ((float4*)(g_X + (size_t)row * D_))[t] = o;
}

__global__ void k_final(const float* __restrict__ resid, const float* __restrict__ ln_g,
                        const float* __restrict__ ln_b, float* __restrict__ out) {
    int row = blockIdx.x;
    int t = threadIdx.x;
    float4 v = ((const float4*)(g_O + (size_t)row * D_))[t];
    float4 r = ((const float4*)(resid + (size_t)row * D_))[t];
    v.x += r.x; v.y += r.y; v.z += r.z; v.w += r.w;
    __shared__ float red[128];

    red[t] = v.x + v.y + v.z + v.w;
    __syncthreads();
    for (int s = 64; s > 0; s >>= 1) {
        if (t < s) red[t] += red[t + s];
        __syncthreads();
    }
    float mean = red[0] * (1.0f / D_);
    __syncthreads();

    float dx = v.x - mean, dy = v.y - mean, dz = v.z - mean, dw = v.w - mean;
    red[t] = dx * dx + dy * dy + dz * dz + dw * dw;
    __syncthreads();
    for (int s = 64; s > 0; s >>= 1) {
        if (t < s) red[t] += red[t + s];
        __syncthreads();
    }
    float rstd = rsqrtf(red[0] * (1.0f / D_) + 1e-6f);

    float4 g4 = ((const float4*)ln_g)[t];
    float4 b4 = ((const float4*)ln_b)[t];
    float4 o;
    o.x = dx * rstd * g4.x + b4.x;
    o.y = dy * rstd * g4.y + b4.y;
    o.z = dz * rstd * g4.z + b4.z;
    o.w = dw * rstd * g4.w + b4.w;
    ((float4*)(out + (size_t)row * D_))[t] = o;
}

// ---------------------------------------------------------------------------
extern "C" void kernel_launch(void* const* d_in, const int* in_sizes, int n_in,
                              void* d_out, int out_size) {
    const float* q      = (const float*)d_in[0];
    const float* k      = (const float*)d_in[1];
    const float* v      = (const float*)d_in[2];
    const float* latent = (const float*)d_in[3];
    const float* Wq  = (const float*)d_in[4];
    const float* bq  = (const float*)d_in[5];
    const float* Wk  = (const float*)d_in[6];
    const float* bk  = (const float*)d_in[7];
    const float* Wv  = (const float*)d_in[8];
    const float* bv  = (const float*)d_in[9];
    const float* Wfc = (const float*)d_in[10];
    const float* bfc = (const float*)d_in[11];
    const float* Ws1 = (const float*)d_in[12];
    const float* bs1 = (const float*)d_in[13];
    const float* Ws2 = (const float*)d_in[14];
    const float* bs2 = (const float*)d_in[15];
    const float* en_g = (const float*)d_in[16];
    const float* en_b = (const float*)d_in[17];
    const float* ln_g = (const float*)d_in[18];
    const float* ln_b = (const float*)d_in[19];

    float* out  = (float*)d_out;
    float* attn = out + ATT_OFF;

    cudaFuncSetAttribute(k_proj_qkv, cudaFuncAttributeMaxDynamicSharedMemorySize, SMEM_BIG);
    cudaFuncSetAttribute(k_fc,   cudaFuncAttributeMaxDynamicSharedMemorySize, SMEM_BIG);
    cudaFuncSetAttribute(k_s2,   cudaFuncAttributeMaxDynamicSharedMemorySize, SMEM_BIG);
    cudaFuncSetAttribute(k_scores, cudaFuncAttributeMaxDynamicSharedMemorySize, SMEM_SC);
    cudaFuncSetAttribute(k_attnv, cudaFuncAttributeMaxDynamicSharedMemorySize, SMEM_AV);

    dim3 t256(NTHR);
    dim3 gBig(D_ / 128, BL_ / 128);         // (4, 64)

    k_round<<<dim3(D_ * D_ / 1024, 5), 256>>>(Wq, Wk, Wv, Wfc, Ws2);

    k_proj_qkv<<<dim3(D_ / 128, BL_ / 128, 3), t256, SMEM_BIG>>>(
        q, k, v, bq, bk, bv);

    k_scores<<<dim3(L_ / 64, L_ / 128, B_ * H_), t256, SMEM_SC>>>(attn);
    k_attnv<<<dim3(L_ / 64, B_ * H_), t256, SMEM_AV>>>(attn);

    k_fc<<<gBig, t256, SMEM_BIG>>>(bfc);
    k_lat<<<dim3(B_, 8), 128>>>(latent, Ws1, bs1);
    k_film<<<BL_, 128>>>(en_g, en_b);
    k_s2<<<gBig, t256, SMEM_BIG>>>(bs2);
    k_final<<<BL_, 128>>>(q, ln_g, ln_b, out);
}

// round 13
// speedup vs baseline: 1.1653x; 1.0143x over previous
#include <cuda_runtime.h>
#include <cstdint>

// Problem dims
#define B_ 8
#define L_ 1024
#define D_ 512
#define H_ 8
#define DK_ 64
#define BL_ (B_ * L_)               // 8192
#define ATT_OFF ((size_t)BL_ * D_)  // start of attn in d_out

#define NTHR 256

// attnv tile (64x64), 3-stage pipeline
#define AV_ASZ (64 * 36)
#define AV_BSZ (32 * 72)
#define SMEM_AV ((3 * AV_ASZ + 3 * AV_BSZ + 64) * 4)     // 55,552 B

// big GEMM tile (128x128)
#define ABZ (128 * 36)
#define BBZ (32 * 136)
#define SMEM_BIG ((2 * ABZ + 2 * BBZ + 32) * 4)          // 71808 B

#define SMEM_SC   ((128 * 68 + 64 * 68 + 256) * 4)       // scores

// Scratch (static device globals — no allocation)
__device__ float g_Q[BL_ * D_];
__device__ float g_K[BL_ * D_];
__device__ float g_V[BL_ * D_];
__device__ float g_O[BL_ * D_];
__device__ float g_O2[BL_ * D_];
__device__ float g_X[BL_ * D_];
__device__ float g_lat[B_ * 2 * D_];
__device__ float g_psum[(size_t)B_ * H_ * 16 * L_];
__device__ float g_W[5][D_ * D_];    // tf32-rounded Wq,Wk,Wv,Wfc,Ws2

// ---------------------------------------------------------------------------
// helpers
// ---------------------------------------------------------------------------
__device__ __forceinline__ float tf32r(float x) {
    uint32_t o;
    asm("cvt.rna.tf32.f32 %0, %1;" : "=r"(o) : "f"(x));
    return __uint_as_float(o);
}

__device__ __forceinline__ void mma_tf32(float c[4], const float a[4], const float b[2]) {
    asm volatile(
        "mma.sync.aligned.m16n8k8.row.col.f32.tf32.tf32.f32 "
        "{%0,%1,%2,%3}, {%4,%5,%6,%7}, {%8,%9}, {%0,%1,%2,%3};"
        : "+f"(c[0]), "+f"(c[1]), "+f"(c[2]), "+f"(c[3])
        : "r"(__float_as_uint(a[0])), "r"(__float_as_uint(a[1])),
          "r"(__float_as_uint(a[2])), "r"(__float_as_uint(a[3])),
          "r"(__float_as_uint(b[0])), "r"(__float_as_uint(b[1])));
}

__device__ __forceinline__ void cp16(float* dst_smem, const float* src) {
    uint32_t d = (uint32_t)__cvta_generic_to_shared(dst_smem);
    asm volatile("cp.async.cg.shared.global [%0], [%1], 16;" :: "r"(d), "l"(src));
}
#define CP_COMMIT() asm volatile("cp.async.commit_group;")
#define CP_WAIT0()  asm volatile("cp.async.wait_group 0;")
#define CP_WAIT1()  asm volatile("cp.async.wait_group 1;")
#define CP_WAIT2()  asm volatile("cp.async.wait_group 2;")

// ---------------------------------------------------------------------------
// weight pre-round: g_W[m] = tf32r(W_m). grid (256, 5), 256 thr.
// ---------------------------------------------------------------------------
__global__ void k_round(const float* __restrict__ w0, const float* __restrict__ w1,
                        const float* __restrict__ w2, const float* __restrict__ w3,
                        const float* __restrict__ w4) {
    const float* srcs[5] = {w0, w1, w2, w3, w4};
    int m = blockIdx.y;
    int i = (blockIdx.x * 256 + threadIdx.x) * 4;
    float4 v = *(const float4*)(srcs[m] + i);
    v.x = tf32r(v.x); v.y = tf32r(v.y); v.z = tf32r(v.z); v.w = tf32r(v.w);
    *(float4*)(&g_W[m][i]) = v;
}

// ---------------------------------------------------------------------------
// attnv: O = (E @ V) * rinv, writing normalized attn back as E streams
// through. 64x64 tile, 3-stage cp.async, heads processed in REVERSE order
// (freshest E from k_scores is still L2-resident). rinv computed inline.
// O stored tf32-rounded (fc consumes without cvt).
// ---------------------------------------------------------------------------
__global__ void __launch_bounds__(NTHR) k_attnv(float* __restrict__ attn) {
    extern __shared__ float sm[];
    float* Asm = sm;                    // [3][64][36]
    float* Bsm = sm + 3 * AV_ASZ;       // [3][32][72]
    float* sRinv = Bsm + 3 * AV_BSZ;    // [64]

    const int t = threadIdx.x;
    const int lane = t & 31, w = t >> 5;
    const int wm = w & 3, wn = w >> 2;      // 4(m:16) x 2(n:32)
    const int g = lane >> 2, tg = lane & 3;
    const int z = (B_ * H_ - 1) - blockIdx.y;   // reversed head order
    const int b = z >> 3, h = z & 7;
    const int row0 = blockIdx.x * 64;

    float* Ag = attn + (size_t)z * L_ * L_;                    // E rows
    const float* Bg = g_V + (size_t)b * L_ * D_ + h * DK_;     // V

    if (t < 64) {
        float s = 0.f;
        #pragma unroll
        for (int ct = 0; ct < 16; ct++)
            s += g_psum[((size_t)z * 16 + ct) * L_ + row0 + t];
        sRinv[t] = 1.0f / s;
    }

    float acc[4][4] = {};

    // prologue: stage chunks 0..2
    #pragma unroll
    for (int c = 0; c < 3; c++) {
        float* Ad = Asm + c * AV_ASZ;
        float* Bd = Bsm + c * AV_BSZ;
        #pragma unroll
        for (int i = 0; i < 2; i++) {
            int idx = t + i * NTHR, r = idx >> 3, c4 = (idx & 7) << 2;
            cp16(Ad + r * 36 + c4, Ag + (size_t)(row0 + r) * L_ + c * 32 + c4);
        }
        #pragma unroll
        for (int i = 0; i < 2; i++) {
            int idx = t + i * NTHR, r = idx >> 4, c4 = (idx & 15) << 2;
            cp16(Bd + r * 72 + c4, Bg + (size_t)(c * 32 + r) * D_ + c4);
        }
        CP_COMMIT();
    }

    for (int i = 0; i < 32; i++) {
        if (i < 30) CP_WAIT2();
        else if (i == 30) CP_WAIT1();
        else CP_WAIT0();
        __syncthreads();

        int buf = i % 3;
        float* Ab = Asm + buf * AV_ASZ;
        float* Bb = Bsm + buf * AV_BSZ;
        int k0 = i * 32;

        // write normalized attn chunk back (coalesced float4)
        #pragma unroll
        for (int j = 0; j < 2; j++) {
            int idx = t + j * NTHR, r = idx >> 3, c4 = (idx & 7) << 2;
            float4 v = *(const float4*)(Ab + r * 36 + c4);
            float s = sRinv[r];
            v.x *= s; v.y *= s; v.z *= s; v.w *= s;
            *(float4*)(Ag + (size_t)(row0 + r) * L_ + k0 + c4) = v;
        }

        #pragma unroll
        for (int ks = 0; ks < 32; ks += 8) {
            float a[4], bf[4][2];
            {
                int r = wm * 16 + g;
                a[0] = tf32r(Ab[r * 36 + ks + tg]);
                a[1] = tf32r(Ab[(r + 8) * 36 + ks + tg]);
                a[2] = tf32r(Ab[r * 36 + ks + tg + 4]);
                a[3] = tf32r(Ab[(r + 8) * 36 + ks + tg + 4]);
            }
            #pragma unroll
            for (int nt = 0; nt < 4; nt++) {
                int n = wn * 32 + nt * 8 + g;
                bf[nt][0] = Bb[(ks + tg) * 72 + n];
                bf[nt][1] = Bb[(ks + tg + 4) * 72 + n];
            }
            #pragma unroll
            for (int nt = 0; nt < 4; nt++)
                mma_tf32(acc[nt], a, bf[nt]);
        }
        __syncthreads();

        if (i + 3 < 32) {
            int kc = i + 3;
            #pragma unroll
            for (int j = 0; j < 2; j++) {
                int idx = t + j * NTHR, r = idx >> 3, c4 = (idx & 7) << 2;
                cp16(Ab + r * 36 + c4, Ag + (size_t)(row0 + r) * L_ + kc * 32 + c4);
            }
            #pragma unroll
            for (int j = 0; j < 2; j++) {
                int idx = t + j * NTHR, r = idx >> 4, c4 = (idx & 15) << 2;
                cp16(Bb + r * 72 + c4, Bg + (size_t)(kc * 32 + r) * D_ + c4);
            }
            CP_COMMIT();
        }
    }

    // epilogue: O rows scaled by rinv, tf32-rounded for fc
    #pragma unroll
    for (int nt = 0; nt < 4; nt++) {
        int rl = wm * 16 + g;
        int c = wn * 32 + nt * 8 + tg * 2;
        float s0 = sRinv[rl], s1 = sRinv[rl + 8];
        float* Og = g_O + (size_t)(b * L_ + row0 + rl) * D_ + h * DK_ + c;
        *(float2*)Og = make_float2(tf32r(acc[nt][0] * s0), tf32r(acc[nt][1] * s0));
        *(float2*)(Og + 8 * D_) =
            make_float2(tf32r(acc[nt][2] * s1), tf32r(acc[nt][3] * s1));
    }
}

// ---------------------------------------------------------------------------
// 128x128 double-buffered GEMM. Warp tile 32x64.
// ACVT: cvt A fragments (raw external inputs). B is always pre-rounded.
// RND: round C to tf32 on store.
// ---------------------------------------------------------------------------
template <bool ACVT, bool RND>
__device__ __forceinline__ void gemm_big(
    const float* __restrict__ A, const float* __restrict__ Bg,
    const float* __restrict__ bias, float* __restrict__ C,
    int K, int lda, int ldb, int ldc)
{
    extern __shared__ float sm[];
    float* Asm = sm;                    // [2][128][36]
    float* Bsm = sm + 2 * ABZ;          // [2][32][136]

    const int t = threadIdx.x;
    const int lane = t & 31, w = t >> 5;
    const int wm = w & 3, wn = w >> 2;          // 4(m) x 2(n)
    const int g = lane >> 2, tg = lane & 3;
    const int row0 = blockIdx.y * 128;
    const int col0 = blockIdx.x * 128;

    float acc[2][8][4] = {};

    {
        #pragma unroll
        for (int i = 0; i < 4; i++) {
            int idx = t + i * NTHR, r = idx >> 3, c4 = (idx & 7) << 2;
            cp16(Asm + r * 36 + c4, A + (size_t)(row0 + r) * lda + c4);
        }
        #pragma unroll
        for (int i = 0; i < 4; i++) {
            int idx = t + i * NTHR, r = idx >> 5, c4 = (idx & 31) << 2;
            cp16(Bsm + r * 136 + c4, Bg + (size_t)r * ldb + col0 + c4);
        }
        CP_COMMIT();
    }

    int buf = 0;
    for (int k0 = 0; k0 < K; k0 += 32) {
        if (k0 + 32 < K) {
            float* Ad = Asm + (buf ^ 1) * ABZ;
            float* Bd = Bsm + (buf ^ 1) * BBZ;
            int kn = k0 + 32;
            #pragma unroll
            for (int i = 0; i < 4; i++) {
                int idx = t + i * NTHR, r = idx >> 3, c4 = (idx & 7) << 2;
                cp16(Ad + r * 36 + c4, A + (size_t)(row0 + r) * lda + kn + c4);
            }
            #pragma unroll
            for (int i = 0; i < 4; i++) {
                int idx = t + i * NTHR, r = idx >> 5, c4 = (idx & 31) << 2;
                cp16(Bd + r * 136 + c4, Bg + (size_t)(kn + r) * ldb + col0 + c4);
            }
            CP_COMMIT();
            CP_WAIT1();
        } else {
            CP_WAIT0();
        }
        __syncthreads();

        float* Ab = Asm + buf * ABZ;
        float* Bb = Bsm + buf * BBZ;

        #pragma unroll
        for (int ks = 0; ks < 32; ks += 8) {
            float a[2][4], bf[8][2];
            #pragma unroll
            for (int mt = 0; mt < 2; mt++) {
                int r = wm * 32 + mt * 16 + g;
                if (ACVT) {
                    a[mt][0] = tf32r(Ab[r * 36 + ks + tg]);
                    a[mt][1] = tf32r(Ab[(r + 8) * 36 + ks + tg]);
                    a[mt][2] = tf32r(Ab[r * 36 + ks + tg + 4]);
                    a[mt][3] = tf32r(Ab[(r + 8) * 36 + ks + tg + 4]);
                } else {
                    a[mt][0] = Ab[r * 36 + ks + tg];
                    a[mt][1] = Ab[(r + 8) * 36 + ks + tg];
                    a[mt][2] = Ab[r * 36 + ks + tg + 4];
                    a[mt][3] = Ab[(r + 8) * 36 + ks + tg + 4];
                }
            }
            #pragma unroll
            for (int nt = 0; nt < 8; nt++) {
                int n = wn * 64 + nt * 8 + g;
                bf[nt][0] = Bb[(ks + tg) * 136 + n];
                bf[nt][1] = Bb[(ks + tg + 4) * 136 + n];
            }
            #pragma unroll
            for (int mt = 0; mt < 2; mt++)
                #pragma unroll
                for (int nt = 0; nt < 8; nt++)
                    mma_tf32(acc[mt][nt], a[mt], bf[nt]);
        }
        __syncthreads();
        buf ^= 1;
    }

    #pragma unroll
    for (int mt = 0; mt < 2; mt++) {
        #pragma unroll
        for (int nt = 0; nt < 8; nt++) {
            int r = row0 + wm * 32 + mt * 16 + g;
            int c = col0 + wn * 64 + nt * 8 + tg * 2;
            float b0 = 0.f, b1 = 0.f;
            if (bias) { b0 = bias[c]; b1 = bias[c + 1]; }
            float o0 = acc[mt][nt][0] + b0, o1 = acc[mt][nt][1] + b1;
            float o2 = acc[mt][nt][2] + b0, o3 = acc[mt][nt][3] + b1;
            if (RND) { o0 = tf32r(o0); o1 = tf32r(o1); o2 = tf32r(o2); o3 = tf32r(o3); }
            *(float2*)(C + (size_t)r * ldc + c) = make_float2(o0, o1);
            *(float2*)(C + (size_t)(r + 8) * ldc + c) = make_float2(o2, o3);
        }
    }
}

// ---------------------------------------------------------------------------
// scores: E = exp(QK^T/8), staged coalesced write + partial row sums.
// ---------------------------------------------------------------------------
__global__ void __launch_bounds__(256) k_scores(float* __restrict__ attn) {
    extern __shared__ float sm[];
    float* Qs = sm;                     // [128][68], reused to stage E
    float* Ks = sm + 128 * 68;          // [64][68]
    float* sPart = Ks + 64 * 68;        // [2][128]

    const int t = threadIdx.x;
    const int lane = t & 31, w = t >> 5;
    const int wm = w & 3, wn = w >> 2;
    const int g = lane >> 2, tg = lane & 3;
    const int z = blockIdx.z, b = z >> 3, h = z & 7;
    const int row0 = blockIdx.y * 128;
    const int col0 = blockIdx.x * 64;

    const float* Qg = g_Q + (size_t)b * L_ * D_ + h * DK_;
    const float* Kg = g_K + (size_t)b * L_ * D_ + h * DK_;
    float* attn_b = attn + (size_t)z * L_ * L_;

    #pragma unroll
    for (int i = 0; i < 8; i++) {
        int idx = t + i * 256, r = idx >> 4, c4 = (idx & 15) << 2;
        cp16(Qs + r * 68 + c4, Qg + (size_t)(row0 + r) * D_ + c4);
    }
    #pragma unroll
    for (int i = 0; i < 4; i++) {
        int idx = t + i * 256, r = idx >> 4, c4 = (idx & 15) << 2;
        cp16(Ks + r * 68 + c4, Kg + (size_t)(col0 + r) * D_ + c4);
    }
    CP_COMMIT();
    CP_WAIT0();
    __syncthreads();

    float acc[2][4][4] = {};
    #pragma unroll
    for (int ks = 0; ks < DK_; ks += 8) {
        float a[2][4], bf[4][2];
        #pragma unroll
        for (int mt = 0; mt < 2; mt++) {
            int r = wm * 32 + mt * 16 + g;
            a[mt][0] = Qs[r * 68 + ks + tg];
            a[mt][1] = Qs[(r + 8) * 68 + ks + tg];
            a[mt][2] = Qs[r * 68 + ks + tg + 4];
            a[mt][3] = Qs[(r + 8) * 68 + ks + tg + 4];
        }
        #pragma unroll
        for (int nt = 0; nt < 4; nt++) {
            int n = wn * 32 + nt * 8 + g;
            bf[nt][0] = Ks[n * 68 + ks + tg];
            bf[nt][1] = Ks[n * 68 + ks + tg + 4];
        }
        #pragma unroll
        for (int mt = 0; mt < 2; mt++)
            #pragma unroll
            for (int nt = 0; nt < 4; nt++)
                mma_tf32(acc[mt][nt], a[mt], bf[nt]);
    }
    __syncthreads();

    float rs[2][2] = {};
    #pragma unroll
    for (int mt = 0; mt < 2; mt++) {
        int rl = wm * 32 + mt * 16 + g;
        #pragma unroll
        for (int nt = 0; nt < 4; nt++) {
            int c = wn * 32 + nt * 8 + tg * 2;
            float e0 = __expf(acc[mt][nt][0] * 0.125f);
            float e1 = __expf(acc[mt][nt][1] * 0.125f);
            float e2 = __expf(acc[mt][nt][2] * 0.125f);
            float e3 = __expf(acc[mt][nt][3] * 0.125f);
            Qs[rl * 68 + c]           = e0;
            Qs[rl * 68 + c + 1]       = e1;
            Qs[(rl + 8) * 68 + c]     = e2;
            Qs[(rl + 8) * 68 + c + 1] = e3;
            rs[mt][0] += e0 + e1;
            rs[mt][1] += e2 + e3;
        }
    }
    #pragma unroll
    for (int mt = 0; mt < 2; mt++) {
        #pragma unroll
        for (int j = 0; j < 2; j++) {
            rs[mt][j] += __shfl_xor_sync(~0u, rs[mt][j], 1);
            rs[mt][j] += __shfl_xor_sync(~0u, rs[mt][j], 2);
        }
        if (tg == 0) {
            int rl = wm * 32 + mt * 16 + g;
            sPart[wn * 128 + rl] = rs[mt][0];
            sPart[wn * 128 + rl + 8] = rs[mt][1];
        }
    }
    __syncthreads();

    #pragma unroll
    for (int i = 0; i < 8; i++) {
        int idx = t + i * 256, r = idx >> 4, c4 = (idx & 15) << 2;
        *(float4*)(attn_b + (size_t)(row0 + r) * L_ + col0 + c4) =
            *(const float4*)(Qs + r * 68 + c4);
    }
    if (t < 128)
        g_psum[((size_t)z * 16 + blockIdx.x) * L_ + row0 + t] =
            sPart[t] + sPart[128 + t];
}

// ---------------------------------------------------------------------------
// GEMM wrappers
// ---------------------------------------------------------------------------
__global__ void __launch_bounds__(NTHR, 2) k_proj_qkv(
        const float* __restrict__ q, const float* __restrict__ k,
        const float* __restrict__ v,
        const float* __restrict__ bq, const float* __restrict__ bk,
        const float* __restrict__ bv) {
    int z = blockIdx.z;
    const float* A = (z == 0) ? q : (z == 1) ? k : v;
    const float* bias = (z == 0) ? bq : (z == 1) ? bk : bv;
    float* C = (z == 0) ? g_Q : (z == 1) ? g_K : g_V;
    gemm_big<true, true>(A, g_W[z], bias, C, D_, D_, D_, D_);
}

__global__ void __launch_bounds__(NTHR, 2) k_fc(const float* __restrict__ bias) {
    gemm_big<false, false>(g_O, g_W[3], bias, g_O2, D_, D_, D_, D_);
}
__global__ void __launch_bounds__(NTHR, 2) k_s2(const float* __restrict__ bias) {
    gemm_big<false, false>(g_X, g_W[4], bias, g_O, D_, D_, D_, D_);
}

// ---------------------------------------------------------------------------
// small epilogues
// ---------------------------------------------------------------------------
__global__ void k_lat(const float* __restrict__ latent, const float* __restrict__ Ws1,
                      const float* __restrict__ bs1) {
    int b = blockIdx.x;
    __shared__ float sl[D_];
    for (int i = threadIdx.x; i < D_; i += 128) {
        float x = latent[b * D_ + i];
        sl[i] = x / (1.0f + __expf(-x));
    }
    __syncthreads();
    int j = blockIdx.y * 128 + threadIdx.x;
    float acc = bs1[j];
    for (int k = 0; k < D_; k++) acc += sl[k] * Ws1[(size_t)k * (2 * D_) + j];
    g_lat[b * (2 * D_) + j] = acc;
}

// film: X = tf32r(silu(LN(o2)*(1+scale)+shift)) — s2 consumes without cvt
__global__ void k_film(const float* __restrict__ en_g, const float* __restrict__ en_b) {
    int row = blockIdx.x;
    int b = row >> 10;
    int t = threadIdx.x;
    float4 v = ((const float4*)(g_O2 + (size_t)row * D_))[t];
    __shared__ float red[128];

    red[t] = v.x + v.y + v.z + v.w;
    __syncthreads();
    for (int s = 64; s > 0; s >>= 1) {
        if (t < s) red[t] += red[t + s];
        __syncthreads();
    }
    float mean = red[0] * (1.0f / D_);
    __syncthreads();

    float dx = v.x - mean, dy = v.y - mean, dz = v.z - mean, dw = v.w - mean;
    red[t] = dx * dx + dy * dy + dz * dz + dw * dw;
    __syncthreads();
    for (int s = 64; s > 0; s >>= 1) {
        if (t < s) red[t] += red[t + s];
        __syncthreads();
    }
    float rstd = rsqrtf(red[0] * (1.0f / D_) + 1e-5f);

    int j = t * 4;
    float4 g4 = ((const float4*)en_g)[t];
    float4 b4 = ((const float4*)en_b)[t];
    float4 sc = *(const float4*)(g_lat + b * (2 * D_) + j);
    float4 sh = *(const float4*)(g_lat + b * (2 * D_) + D_ + j);

    float4 o;
    {
        float h;
        h = (dx * rstd * g4.x + b4.x) * (1.0f + sc.x) + sh.x; o.x = tf32r(h / (1.0f + __expf(-h)));
        h = (dy * rstd * g4.y + b4.y) * (1.0f + sc.y) + sh.y; o.y = tf32r(h / (1.0f + __expf(-h)));
        h = (dz * rstd * g4.z + b4.z) * (1.0f + sc.z) + sh.z; o.z = tf32r(h / (1.0f + __expf(-h)));
        h = (dw * rstd * g4.w + b4.w) * (1.0f + sc.w) + sh.w; o.w = tf32r(h / (1.0f + __expf(-h)));
    }
    ((float4*)(g_X + (size_t)row * D_))[t] = o;
}

__global__ void k_final(const float* __restrict__ resid, const float* __restrict__ ln_g,
                        const float* __restrict__ ln_b, float* __restrict__ out) {
    int row = blockIdx.x;
    int t = threadIdx.x;
    float4 v = ((const float4*)(g_O + (size_t)row * D_))[t];
    float4 r = ((const float4*)(resid + (size_t)row * D_))[t];
    v.x += r.x; v.y += r.y; v.z += r.z; v.w += r.w;
    __shared__ float red[128];

    red[t] = v.x + v.y + v.z + v.w;
    __syncthreads();
    for (int s = 64; s > 0; s >>= 1) {
        if (t < s) red[t] += red[t + s];
        __syncthreads();
    }
    float mean = red[0] * (1.0f / D_);
    __syncthreads();

    float dx = v.x - mean, dy = v.y - mean, dz = v.z - mean, dw = v.w - mean;
    red[t] = dx * dx + dy * dy + dz * dz + dw * dw;
    __syncthreads();
    for (int s = 64; s > 0; s >>= 1) {
        if (t < s) red[t] += red[t + s];
        __syncthreads();
    }
    float rstd = rsqrtf(red[0] * (1.0f / D_) + 1e-6f);

    float4 g4 = ((const float4*)ln_g)[t];
    float4 b4 = ((const float4*)ln_b)[t];
    float4 o;
    o.x = dx * rstd * g4.x + b4.x;
    o.y = dy * rstd * g4.y + b4.y;
    o.z = dz * rstd * g4.z + b4.z;
    o.w = dw * rstd * g4.w + b4.w;
    ((float4*)(out + (size_t)row * D_))[t] = o;
}

// ---------------------------------------------------------------------------
extern "C" void kernel_launch(void* const* d_in, const int* in_sizes, int n_in,
                              void* d_out, int out_size) {
    const float* q      = (const float*)d_in[0];
    const float* k      = (const float*)d_in[1];
    const float* v      = (const float*)d_in[2];
    const float* latent = (const float*)d_in[3];
    const float* Wq  = (const float*)d_in[4];
    const float* bq  = (const float*)d_in[5];
    const float* Wk  = (const float*)d_in[6];
    const float* bk  = (const float*)d_in[7];
    const float* Wv  = (const float*)d_in[8];
    const float* bv  = (const float*)d_in[9];
    const float* Wfc = (const float*)d_in[10];
    const float* bfc = (const float*)d_in[11];
    const float* Ws1 = (const float*)d_in[12];
    const float* bs1 = (const float*)d_in[13];
    const float* Ws2 = (const float*)d_in[14];
    const float* bs2 = (const float*)d_in[15];
    const float* en_g = (const float*)d_in[16];
    const float* en_b = (const float*)d_in[17];
    const float* ln_g = (const float*)d_in[18];
    const float* ln_b = (const float*)d_in[19];

    float* out  = (float*)d_out;
    float* attn = out + ATT_OFF;

    cudaFuncSetAttribute(k_proj_qkv, cudaFuncAttributeMaxDynamicSharedMemorySize, SMEM_BIG);
    cudaFuncSetAttribute(k_fc,   cudaFuncAttributeMaxDynamicSharedMemorySize, SMEM_BIG);
    cudaFuncSetAttribute(k_s2,   cudaFuncAttributeMaxDynamicSharedMemorySize, SMEM_BIG);
    cudaFuncSetAttribute(k_scores, cudaFuncAttributeMaxDynamicSharedMemorySize, SMEM_SC);
    cudaFuncSetAttribute(k_attnv, cudaFuncAttributeMaxDynamicSharedMemorySize, SMEM_AV);

    dim3 t256(NTHR);
    dim3 gBig(D_ / 128, BL_ / 128);         // (4, 64)

    k_round<<<dim3(D_ * D_ / 1024, 5), 256>>>(Wq, Wk, Wv, Wfc, Ws2);

    k_proj_qkv<<<dim3(D_ / 128, BL_ / 128, 3), t256, SMEM_BIG>>>(
        q, k, v, bq, bk, bv);

    k_scores<<<dim3(L_ / 64, L_ / 128, B_ * H_), t256, SMEM_SC>>>(attn);
    k_attnv<<<dim3(L_ / 64, B_ * H_), t256, SMEM_AV>>>(attn);

    k_fc<<<gBig, t256, SMEM_BIG>>>(bfc);
    k_lat<<<dim3(B_, 8), 128>>>(latent, Ws1, bs1);
    k_film<<<BL_, 128>>>(en_g, en_b);
    k_s2<<<gBig, t256, SMEM_BIG>>>(bs2);
    k_final<<<BL_, 128>>>(q, ln_g, ln_b, out);
}

// round 14
// speedup vs baseline: 1.1811x; 1.0136x over previous
#include <cuda_runtime.h>
#include <cstdint>

// Problem dims
#define B_ 8
#define L_ 1024
#define D_ 512
#define H_ 8
#define DK_ 64
#define BL_ (B_ * L_)               // 8192
#define ATT_OFF ((size_t)BL_ * D_)  // start of attn in d_out

#define NTHR 256

// attnv tile (64x64), 3-stage pipeline
#define AV_ASZ (64 * 36)
#define AV_BSZ (32 * 72)
#define SMEM_AV ((3 * AV_ASZ + 3 * AV_BSZ + 64) * 4)     // 55,552 B

// big GEMM tile (128x128)
#define ABZ (128 * 36)
#define BBZ (32 * 136)
#define SMEM_BIG ((2 * ABZ + 2 * BBZ + 32) * 4)          // 71808 B

// scores (full-row, 64 rows/CTA): Qs[64][68] Es[64][68] Ks[2][64][68] sPart[4][64]
#define SC_QS 0
#define SC_ES (64 * 68)
#define SC_KS (SC_ES + 64 * 68)
#define SC_SP (SC_KS + 2 * 64 * 68)
#define SMEM_SC ((SC_SP + 4 * 64) * 4)                   // 70,656 B

// Scratch (static device globals — no allocation)
__device__ float g_Q[BL_ * D_];
__device__ float g_K[BL_ * D_];
__device__ float g_V[BL_ * D_];
__device__ float g_O[BL_ * D_];
__device__ float g_O2[BL_ * D_];
__device__ float g_X[BL_ * D_];
__device__ float g_lat[B_ * 2 * D_];
__device__ float g_rinv[(size_t)B_ * H_ * L_];
__device__ float g_W[5][D_ * D_];    // tf32-rounded Wq,Wk,Wv,Wfc,Ws2

// ---------------------------------------------------------------------------
// helpers
// ---------------------------------------------------------------------------
__device__ __forceinline__ float tf32r(float x) {
    uint32_t o;
    asm("cvt.rna.tf32.f32 %0, %1;" : "=r"(o) : "f"(x));
    return __uint_as_float(o);
}

__device__ __forceinline__ void mma_tf32(float c[4], const float a[4], const float b[2]) {
    asm volatile(
        "mma.sync.aligned.m16n8k8.row.col.f32.tf32.tf32.f32 "
        "{%0,%1,%2,%3}, {%4,%5,%6,%7}, {%8,%9}, {%0,%1,%2,%3};"
        : "+f"(c[0]), "+f"(c[1]), "+f"(c[2]), "+f"(c[3])
        : "r"(__float_as_uint(a[0])), "r"(__float_as_uint(a[1])),
          "r"(__float_as_uint(a[2])), "r"(__float_as_uint(a[3])),
          "r"(__float_as_uint(b[0])), "r"(__float_as_uint(b[1])));
}

__device__ __forceinline__ void cp16(float* dst_smem, const float* src) {
    uint32_t d = (uint32_t)__cvta_generic_to_shared(dst_smem);
    asm volatile("cp.async.cg.shared.global [%0], [%1], 16;" :: "r"(d), "l"(src));
}
#define CP_COMMIT() asm volatile("cp.async.commit_group;")
#define CP_WAIT0()  asm volatile("cp.async.wait_group 0;")
#define CP_WAIT1()  asm volatile("cp.async.wait_group 1;")
#define CP_WAIT2()  asm volatile("cp.async.wait_group 2;")

// ---------------------------------------------------------------------------
// weight pre-round: g_W[m] = tf32r(W_m). grid (256, 5), 256 thr.
// ---------------------------------------------------------------------------
__global__ void k_round(const float* __restrict__ w0, const float* __restrict__ w1,
                        const float* __restrict__ w2, const float* __restrict__ w3,
                        const float* __restrict__ w4) {
    const float* srcs[5] = {w0, w1, w2, w3, w4};
    int m = blockIdx.y;
    int i = (blockIdx.x * 256 + threadIdx.x) * 4;
    float4 v = *(const float4*)(srcs[m] + i);
    v.x = tf32r(v.x); v.y = tf32r(v.y); v.z = tf32r(v.z); v.w = tf32r(v.w);
    *(float4*)(&g_W[m][i]) = v;
}

// ---------------------------------------------------------------------------
// scores (full-row): one CTA owns 64 rows x all 1024 cols of E = exp(QK^T/8).
// Q resident in smem; K chunks (64 keys) 2-stage pipelined; E staged + written
// coalesced; complete rowsum finished in-kernel -> g_rinv. grid (16, 64).
// Warp grid 2(m:32) x 4(n:16). Q/K pre-rounded (no cvt).
// ---------------------------------------------------------------------------
__global__ void __launch_bounds__(256) k_scores(float* __restrict__ attn) {
    extern __shared__ float sm[];
    float* Qs = sm + SC_QS;     // [64][68]
    float* Es = sm + SC_ES;     // [64][68]
    float* Ks = sm + SC_KS;     // [2][64][68]
    float* sPart = sm + SC_SP;  // [4][64]

    const int t = threadIdx.x;
    const int lane = t & 31, w = t >> 5;
    const int wm = w & 1, wn = w >> 1;      // 2 x 4
    const int g = lane >> 2, tg = lane & 3;
    const int z = blockIdx.y, b = z >> 3, h = z & 7;
    const int row0 = blockIdx.x * 64;

    const float* Qg = g_Q + (size_t)b * L_ * D_ + h * DK_;
    const float* Kg = g_K + (size_t)b * L_ * D_ + h * DK_;
    float* attn_b = attn + (size_t)z * L_ * L_;

    // prologue: Q tile (group 1), K chunk 0 (group 2)
    #pragma unroll
    for (int i = 0; i < 4; i++) {
        int idx = t + i * 256, r = idx >> 4, c4 = (idx & 15) << 2;
        cp16(Qs + r * 68 + c4, Qg + (size_t)(row0 + r) * D_ + c4);
    }
    CP_COMMIT();
    #pragma unroll
    for (int i = 0; i < 4; i++) {
        int idx = t + i * 256, r = idx >> 4, c4 = (idx & 15) << 2;
        cp16(Ks + r * 68 + c4, Kg + (size_t)r * D_ + c4);
    }
    CP_COMMIT();

    float rs[2][2] = {};    // rowsum partials: [mt][row g / g+8]

    for (int kc = 0; kc < 16; kc++) {
        int buf = kc & 1;
        if (kc < 15) {
            float* Kd = Ks + (buf ^ 1) * (64 * 68);
            #pragma unroll
            for (int i = 0; i < 4; i++) {
                int idx = t + i * 256, r = idx >> 4, c4 = (idx & 15) << 2;
                cp16(Kd + r * 68 + c4, Kg + (size_t)((kc + 1) * 64 + r) * D_ + c4);
            }
            CP_COMMIT();
            CP_WAIT1();
        } else {
            CP_WAIT0();
        }
        __syncthreads();    // K_kc ready; also WAR barrier for Es and Ks[buf^1]

        float* Kb = Ks + buf * (64 * 68);

        // S tile (64 x 64)
        float acc[2][2][4] = {};
        #pragma unroll
        for (int ks = 0; ks < DK_; ks += 8) {
            float a[2][4], bf[2][2];
            #pragma unroll
            for (int mt = 0; mt < 2; mt++) {
                int r = wm * 32 + mt * 16 + g;
                a[mt][0] = Qs[r * 68 + ks + tg];
                a[mt][1] = Qs[(r + 8) * 68 + ks + tg];
                a[mt][2] = Qs[r * 68 + ks + tg + 4];
                a[mt][3] = Qs[(r + 8) * 68 + ks + tg + 4];
            }
            #pragma unroll
            for (int nt = 0; nt < 2; nt++) {
                int n = wn * 16 + nt * 8 + g;
                bf[nt][0] = Kb[n * 68 + ks + tg];
                bf[nt][1] = Kb[n * 68 + ks + tg + 4];
            }
            #pragma unroll
            for (int mt = 0; mt < 2; mt++)
                #pragma unroll
                for (int nt = 0; nt < 2; nt++)
                    mma_tf32(acc[mt][nt], a[mt], bf[nt]);
        }

        // exp + stage into Es + accumulate rowsums
        #pragma unroll
        for (int mt = 0; mt < 2; mt++) {
            int rl = wm * 32 + mt * 16 + g;
            #pragma unroll
            for (int nt = 0; nt < 2; nt++) {
                int c = wn * 16 + nt * 8 + tg * 2;
                float e0 = __expf(acc[mt][nt][0] * 0.125f);
                float e1 = __expf(acc[mt][nt][1] * 0.125f);
                float e2 = __expf(acc[mt][nt][2] * 0.125f);
                float e3 = __expf(acc[mt][nt][3] * 0.125f);
                Es[rl * 68 + c]           = e0;
                Es[rl * 68 + c + 1]       = e1;
                Es[(rl + 8) * 68 + c]     = e2;
                Es[(rl + 8) * 68 + c + 1] = e3;
                rs[mt][0] += e0 + e1;
                rs[mt][1] += e2 + e3;
            }
        }
        __syncthreads();    // Es staged

        // coalesced write: 64 rows x 64 cols
        #pragma unroll
        for (int i = 0; i < 4; i++) {
            int idx = t + i * 256, r = idx >> 4, c4 = (idx & 15) << 2;
            *(float4*)(attn_b + (size_t)(row0 + r) * L_ + kc * 64 + c4) =
                *(const float4*)(Es + r * 68 + c4);
        }
    }

    // finish rowsums: quad-reduce, cross-warp over wn, write rinv
    #pragma unroll
    for (int mt = 0; mt < 2; mt++) {
        #pragma unroll
        for (int j = 0; j < 2; j++) {
            rs[mt][j] += __shfl_xor_sync(~0u, rs[mt][j], 1);
            rs[mt][j] += __shfl_xor_sync(~0u, rs[mt][j], 2);
        }
        if (tg == 0) {
            int rl = wm * 32 + mt * 16 + g;
            sPart[wn * 64 + rl] = rs[mt][0];
            sPart[wn * 64 + rl + 8] = rs[mt][1];
        }
    }
    __syncthreads();
    if (t < 64) {
        float s = sPart[t] + sPart[64 + t] + sPart[128 + t] + sPart[192 + t];
        g_rinv[(size_t)z * L_ + row0 + t] = 1.0f / s;
    }
}

// ---------------------------------------------------------------------------
// attnv: O = (E @ V) * rinv, writing normalized attn back as E streams
// through. 64x64 tile, 3-stage cp.async, heads in REVERSE order (L2 reuse
// of freshest E). rinv read directly. O stored tf32-rounded.
// ---------------------------------------------------------------------------
__global__ void __launch_bounds__(NTHR) k_attnv(float* __restrict__ attn) {
    extern __shared__ float sm[];
    float* Asm = sm;                    // [3][64][36]
    float* Bsm = sm + 3 * AV_ASZ;       // [3][32][72]
    float* sRinv = Bsm + 3 * AV_BSZ;    // [64]

    const int t = threadIdx.x;
    const int lane = t & 31, w = t >> 5;
    const int wm = w & 3, wn = w >> 2;      // 4(m:16) x 2(n:32)
    const int g = lane >> 2, tg = lane & 3;
    const int z = (B_ * H_ - 1) - blockIdx.y;   // reversed head order
    const int b = z >> 3, h = z & 7;
    const int row0 = blockIdx.x * 64;

    float* Ag = attn + (size_t)z * L_ * L_;                    // E rows
    const float* Bg = g_V + (size_t)b * L_ * D_ + h * DK_;     // V

    if (t < 64) sRinv[t] = g_rinv[(size_t)z * L_ + row0 + t];

    float acc[4][4] = {};

    // prologue: stage chunks 0..2
    #pragma unroll
    for (int c = 0; c < 3; c++) {
        float* Ad = Asm + c * AV_ASZ;
        float* Bd = Bsm + c * AV_BSZ;
        #pragma unroll
        for (int i = 0; i < 2; i++) {
            int idx = t + i * NTHR, r = idx >> 3, c4 = (idx & 7) << 2;
            cp16(Ad + r * 36 + c4, Ag + (size_t)(row0 + r) * L_ + c * 32 + c4);
        }
        #pragma unroll
        for (int i = 0; i < 2; i++) {
            int idx = t + i * NTHR, r = idx >> 4, c4 = (idx & 15) << 2;
            cp16(Bd + r * 72 + c4, Bg + (size_t)(c * 32 + r) * D_ + c4);
        }
        CP_COMMIT();
    }

    for (int i = 0; i < 32; i++) {
        if (i < 30) CP_WAIT2();
        else if (i == 30) CP_WAIT1();
        else CP_WAIT0();
        __syncthreads();

        int buf = i % 3;
        float* Ab = Asm + buf * AV_ASZ;
        float* Bb = Bsm + buf * AV_BSZ;
        int k0 = i * 32;

        // write normalized attn chunk back (coalesced float4)
        #pragma unroll
        for (int j = 0; j < 2; j++) {
            int idx = t + j * NTHR, r = idx >> 3, c4 = (idx & 7) << 2;
            float4 v = *(const float4*)(Ab + r * 36 + c4);
            float s = sRinv[r];
            v.x *= s; v.y *= s; v.z *= s; v.w *= s;
            *(float4*)(Ag + (size_t)(row0 + r) * L_ + k0 + c4) = v;
        }

        #pragma unroll
        for (int ks = 0; ks < 32; ks += 8) {
            float a[4], bf[4][2];
            {
                int r = wm * 16 + g;
                a[0] = tf32r(Ab[r * 36 + ks + tg]);
                a[1] = tf32r(Ab[(r + 8) * 36 + ks + tg]);
                a[2] = tf32r(Ab[r * 36 + ks + tg + 4]);
                a[3] = tf32r(Ab[(r + 8) * 36 + ks + tg + 4]);
            }
            #pragma unroll
            for (int nt = 0; nt < 4; nt++) {
                int n = wn * 32 + nt * 8 + g;
                bf[nt][0] = Bb[(ks + tg) * 72 + n];
                bf[nt][1] = Bb[(ks + tg + 4) * 72 + n];
            }
            #pragma unroll
            for (int nt = 0; nt < 4; nt++)
                mma_tf32(acc[nt], a, bf[nt]);
        }
        __syncthreads();

        if (i + 3 < 32) {
            int kc = i + 3;
            #pragma unroll
            for (int j = 0; j < 2; j++) {
                int idx = t + j * NTHR, r = idx >> 3, c4 = (idx & 7) << 2;
                cp16(Ab + r * 36 + c4, Ag + (size_t)(row0 + r) * L_ + kc * 32 + c4);
            }
            #pragma unroll
            for (int j = 0; j < 2; j++) {
                int idx = t + j * NTHR, r = idx >> 4, c4 = (idx & 15) << 2;
                cp16(Bb + r * 72 + c4, Bg + (size_t)(kc * 32 + r) * D_ + c4);
            }
            CP_COMMIT();
        }
    }

    // epilogue: O rows scaled by rinv, tf32-rounded for fc
    #pragma unroll
    for (int nt = 0; nt < 4; nt++) {
        int rl = wm * 16 + g;
        int c = wn * 32 + nt * 8 + tg * 2;
        float s0 = sRinv[rl], s1 = sRinv[rl + 8];
        float* Og = g_O + (size_t)(b * L_ + row0 + rl) * D_ + h * DK_ + c;
        *(float2*)Og = make_float2(tf32r(acc[nt][0] * s0), tf32r(acc[nt][1] * s0));
        *(float2*)(Og + 8 * D_) =
            make_float2(tf32r(acc[nt][2] * s1), tf32r(acc[nt][3] * s1));
    }
}

// ---------------------------------------------------------------------------
// 128x128 double-buffered GEMM. Warp tile 32x64.
// ACVT: cvt A fragments (raw external inputs). B is always pre-rounded.
// RND: round C to tf32 on store.
// ---------------------------------------------------------------------------
template <bool ACVT, bool RND>
__device__ __forceinline__ void gemm_big(
    const float* __restrict__ A, const float* __restrict__ Bg,
    const float* __restrict__ bias, float* __restrict__ C,
    int K, int lda, int ldb, int ldc)
{
    extern __shared__ float sm[];
    float* Asm = sm;                    // [2][128][36]
    float* Bsm = sm + 2 * ABZ;          // [2][32][136]

    const int t = threadIdx.x;
    const int lane = t & 31, w = t >> 5;
    const int wm = w & 3, wn = w >> 2;          // 4(m) x 2(n)
    const int g = lane >> 2, tg = lane & 3;
    const int row0 = blockIdx.y * 128;
    const int col0 = blockIdx.x * 128;

    float acc[2][8][4] = {};

    {
        #pragma unroll
        for (int i = 0; i < 4; i++) {
            int idx = t + i * NTHR, r = idx >> 3, c4 = (idx & 7) << 2;
            cp16(Asm + r * 36 + c4, A + (size_t)(row0 + r) * lda + c4);
        }
        #pragma unroll
        for (int i = 0; i < 4; i++) {
            int idx = t + i * NTHR, r = idx >> 5, c4 = (idx & 31) << 2;
            cp16(Bsm + r * 136 + c4, Bg + (size_t)r * ldb + col0 + c4);
        }
        CP_COMMIT();
    }

    int buf = 0;
    for (int k0 = 0; k0 < K; k0 += 32) {
        if (k0 + 32 < K) {
            float* Ad = Asm + (buf ^ 1) * ABZ;
            float* Bd = Bsm + (buf ^ 1) * BBZ;
            int kn = k0 + 32;
            #pragma unroll
            for (int i = 0; i < 4; i++) {
                int idx = t + i * NTHR, r = idx >> 3, c4 = (idx & 7) << 2;
                cp16(Ad + r * 36 + c4, A + (size_t)(row0 + r) * lda + kn + c4);
            }
            #pragma unroll
            for (int i = 0; i < 4; i++) {
                int idx = t + i * NTHR, r = idx >> 5, c4 = (idx & 31) << 2;
                cp16(Bd + r * 136 + c4, Bg + (size_t)(kn + r) * ldb + col0 + c4);
            }
            CP_COMMIT();
            CP_WAIT1();
        } else {
            CP_WAIT0();
        }
        __syncthreads();

        float* Ab = Asm + buf * ABZ;
        float* Bb = Bsm + buf * BBZ;

        #pragma unroll
        for (int ks = 0; ks < 32; ks += 8) {
            float a[2][4], bf[8][2];
            #pragma unroll
            for (int mt = 0; mt < 2; mt++) {
                int r = wm * 32 + mt * 16 + g;
                if (ACVT) {
                    a[mt][0] = tf32r(Ab[r * 36 + ks + tg]);
                    a[mt][1] = tf32r(Ab[(r + 8) * 36 + ks + tg]);
                    a[mt][2] = tf32r(Ab[r * 36 + ks + tg + 4]);
                    a[mt][3] = tf32r(Ab[(r + 8) * 36 + ks + tg + 4]);
                } else {
                    a[mt][0] = Ab[r * 36 + ks + tg];
                    a[mt][1] = Ab[(r + 8) * 36 + ks + tg];
                    a[mt][2] = Ab[r * 36 + ks + tg + 4];
                    a[mt][3] = Ab[(r + 8) * 36 + ks + tg + 4];
                }
            }
            #pragma unroll
            for (int nt = 0; nt < 8; nt++) {
                int n = wn * 64 + nt * 8 + g;
                bf[nt][0] = Bb[(ks + tg) * 136 + n];
                bf[nt][1] = Bb[(ks + tg + 4) * 136 + n];
            }
            #pragma unroll
            for (int mt = 0; mt < 2; mt++)
                #pragma unroll
                for (int nt = 0; nt < 8; nt++)
                    mma_tf32(acc[mt][nt], a[mt], bf[nt]);
        }
        __syncthreads();
        buf ^= 1;
    }

    #pragma unroll
    for (int mt = 0; mt < 2; mt++) {
        #pragma unroll
        for (int nt = 0; nt < 8; nt++) {
            int r = row0 + wm * 32 + mt * 16 + g;
            int c = col0 + wn * 64 + nt * 8 + tg * 2;
            float b0 = 0.f, b1 = 0.f;
            if (bias) { b0 = bias[c]; b1 = bias[c + 1]; }
            float o0 = acc[mt][nt][0] + b0, o1 = acc[mt][nt][1] + b1;
            float o2 = acc[mt][nt][2] + b0, o3 = acc[mt][nt][3] + b1;
            if (RND) { o0 = tf32r(o0); o1 = tf32r(o1); o2 = tf32r(o2); o3 = tf32r(o3); }
            *(float2*)(C + (size_t)r * ldc + c) = make_float2(o0, o1);
            *(float2*)(C + (size_t)(r + 8) * ldc + c) = make_float2(o2, o3);
        }
    }
}

// ---------------------------------------------------------------------------
// GEMM wrappers
// ---------------------------------------------------------------------------
__global__ void __launch_bounds__(NTHR, 2) k_proj_qkv(
        const float* __restrict__ q, const float* __restrict__ k,
        const float* __restrict__ v,
        const float* __restrict__ bq, const float* __restrict__ bk,
        const float* __restrict__ bv) {
    int z = blockIdx.z;
    const float* A = (z == 0) ? q : (z == 1) ? k : v;
    const float* bias = (z == 0) ? bq : (z == 1) ? bk : bv;
    float* C = (z == 0) ? g_Q : (z == 1) ? g_K : g_V;
    gemm_big<true, true>(A, g_W[z], bias, C, D_, D_, D_, D_);
}

__global__ void __launch_bounds__(NTHR, 2) k_fc(const float* __restrict__ bias) {
    gemm_big<false, false>(g_O, g_W[3], bias, g_O2, D_, D_, D_, D_);
}
__global__ void __launch_bounds__(NTHR, 2) k_s2(const float* __restrict__ bias) {
    gemm_big<false, false>(g_X, g_W[4], bias, g_O, D_, D_, D_, D_);
}

// ---------------------------------------------------------------------------
// small epilogues
// ---------------------------------------------------------------------------
__global__ void k_lat(const float* __restrict__ latent, const float* __restrict__ Ws1,
                      const float* __restrict__ bs1) {
    int b = blockIdx.x;
    __shared__ float sl[D_];
    for (int i = threadIdx.x; i < D_; i += 128) {
        float x = latent[b * D_ + i];
        sl[i] = x / (1.0f + __expf(-x));
    }
    __syncthreads();
    int j = blockIdx.y * 128 + threadIdx.x;
    float acc = bs1[j];
    for (int k = 0; k < D_; k++) acc += sl[k] * Ws1[(size_t)k * (2 * D_) + j];
    g_lat[b * (2 * D_) + j] = acc;
}

// film: X = tf32r(silu(LN(o2)*(1+scale)+shift)) — s2 consumes without cvt
__global__ void k_film(const float* __restrict__ en_g, const float* __restrict__ en_b) {
    int row = blockIdx.x;
    int b = row >> 10;
    int t = threadIdx.x;
    float4 v = ((const float4*)(g_O2 + (size_t)row * D_))[t];
    __shared__ float red[128];

    red[t] = v.x + v.y + v.z + v.w;
    __syncthreads();
    for (int s = 64; s > 0; s >>= 1) {
        if (t < s) red[t] += red[t + s];
        __syncthreads();
    }
    float mean = red[0] * (1.0f / D_);
    __syncthreads();

    float dx = v.x - mean, dy = v.y - mean, dz = v.z - mean, dw = v.w - mean;
    red[t] = dx * dx + dy * dy + dz * dz + dw * dw;
    __syncthreads();
    for (int s = 64; s > 0; s >>= 1) {
        if (t < s) red[t] += red[t + s];
        __syncthreads();
    }
    float rstd = rsqrtf(red[0] * (1.0f / D_) + 1e-5f);

    int j = t * 4;
    float4 g4 = ((const float4*)en_g)[t];
    float4 b4 = ((const float4*)en_b)[t];
    float4 sc = *(const float4*)(g_lat + b * (2 * D_) + j);
    float4 sh = *(const float4*)(g_lat + b * (2 * D_) + D_ + j);

    float4 o;
    {
        float h;
        h = (dx * rstd * g4.x + b4.x) * (1.0f + sc.x) + sh.x; o.x = tf32r(h / (1.0f + __expf(-h)));
        h = (dy * rstd * g4.y + b4.y) * (1.0f + sc.y) + sh.y; o.y = tf32r(h / (1.0f + __expf(-h)));
        h = (dz * rstd * g4.z + b4.z) * (1.0f + sc.z) + sh.z; o.z = tf32r(h / (1.0f + __expf(-h)));
        h = (dw * rstd * g4.w + b4.w) * (1.0f + sc.w) + sh.w; o.w = tf32r(h / (1.0f + __expf(-h)));
    }
    ((float4*)(g_X + (size_t)row * D_))[t] = o;
}

__global__ void k_final(const float* __restrict__ resid, const float* __restrict__ ln_g,
                        const float* __restrict__ ln_b, float* __restrict__ out) {
    int row = blockIdx.x;
    int t = threadIdx.x;
    float4 v = ((const float4*)(g_O + (size_t)row * D_))[t];
    float4 r = ((const float4*)(resid + (size_t)row * D_))[t];
    v.x += r.x; v.y += r.y; v.z += r.z; v.w += r.w;
    __shared__ float red[128];

    red[t] = v.x + v.y + v.z + v.w;
    __syncthreads();
    for (int s = 64; s > 0; s >>= 1) {
        if (t < s) red[t] += red[t + s];
        __syncthreads();
    }
    float mean = red[0] * (1.0f / D_);
    __syncthreads();

    float dx = v.x - mean, dy = v.y - mean, dz = v.z - mean, dw = v.w - mean;
    red[t] = dx * dx + dy * dy + dz * dz + dw * dw;
    __syncthreads();
    for (int s = 64; s > 0; s >>= 1) {
        if (t < s) red[t] += red[t + s];
        __syncthreads();
    }
    float rstd = rsqrtf(red[0] * (1.0f / D_) + 1e-6f);

    float4 g4 = ((const float4*)ln_g)[t];
    float4 b4 = ((const float4*)ln_b)[t];
    float4 o;
    o.x = dx * rstd * g4.x + b4.x;
    o.y = dy * rstd * g4.y + b4.y;
    o.z = dz * rstd * g4.z + b4.z;
    o.w = dw * rstd * g4.w + b4.w;
    ((float4*)(out + (size_t)row * D_))[t] = o;
}

// ---------------------------------------------------------------------------
extern "C" void kernel_launch(void* const* d_in, const int* in_sizes, int n_in,
                              void* d_out, int out_size) {
    const float* q      = (const float*)d_in[0];
    const float* k      = (const float*)d_in[1];
    const float* v      = (const float*)d_in[2];
    const float* latent = (const float*)d_in[3];
    const float* Wq  = (const float*)d_in[4];
    const float* bq  = (const float*)d_in[5];
    const float* Wk  = (const float*)d_in[6];
    const float* bk  = (const float*)d_in[7];
    const float* Wv  = (const float*)d_in[8];
    const float* bv  = (const float*)d_in[9];
    const float* Wfc = (const float*)d_in[10];
    const float* bfc = (const float*)d_in[11];
    const float* Ws1 = (const float*)d_in[12];
    const float* bs1 = (const float*)d_in[13];
    const float* Ws2 = (const float*)d_in[14];
    const float* bs2 = (const float*)d_in[15];
    const float* en_g = (const float*)d_in[16];
    const float* en_b = (const float*)d_in[17];
    const float* ln_g = (const float*)d_in[18];
    const float* ln_b = (const float*)d_in[19];

    float* out  = (float*)d_out;
    float* attn = out + ATT_OFF;

    cudaFuncSetAttribute(k_proj_qkv, cudaFuncAttributeMaxDynamicSharedMemorySize, SMEM_BIG);
    cudaFuncSetAttribute(k_fc,   cudaFuncAttributeMaxDynamicSharedMemorySize, SMEM_BIG);
    cudaFuncSetAttribute(k_s2,   cudaFuncAttributeMaxDynamicSharedMemorySize, SMEM_BIG);
    cudaFuncSetAttribute(k_scores, cudaFuncAttributeMaxDynamicSharedMemorySize, SMEM_SC);
    cudaFuncSetAttribute(k_attnv, cudaFuncAttributeMaxDynamicSharedMemorySize, SMEM_AV);

    dim3 t256(NTHR);
    dim3 gBig(D_ / 128, BL_ / 128);         // (4, 64)

    k_round<<<dim3(D_ * D_ / 1024, 5), 256>>>(Wq, Wk, Wv, Wfc, Ws2);

    k_proj_qkv<<<dim3(D_ / 128, BL_ / 128, 3), t256, SMEM_BIG>>>(
        q, k, v, bq, bk, bv);

    k_scores<<<dim3(L_ / 64, B_ * H_), t256, SMEM_SC>>>(attn);
    k_attnv<<<dim3(L_ / 64, B_ * H_), t256, SMEM_AV>>>(attn);

    k_fc<<<gBig, t256, SMEM_BIG>>>(bfc);
    k_lat<<<dim3(B_, 8), 128>>>(latent, Ws1, bs1);
    k_film<<<BL_, 128>>>(en_g, en_b);
    k_s2<<<gBig, t256, SMEM_BIG>>>(bs2);
    k_final<<<BL_, 128>>>(q, ln_g, ln_b, out);
}